// round 1
// baseline (speedup 1.0000x reference)
#include <cuda_runtime.h>
#include <mma.h>

using namespace nvcuda;

// Problem dims: B=8, S=512, D=2048, H=32, HD=64, I=8192, NT=4096 tokens.

// ---------------- scratch (device globals; no allocation allowed) --------
__device__ float g_q  [4096 * 2048];
__device__ float g_k  [4096 * 2048];
__device__ float g_v  [4096 * 2048];
__device__ float g_ctx[4096 * 2048];
__device__ float g_h1 [4096 * 2048];
__device__ float g_tmp[4096 * 8192];   // attn_out -> gate -> act
__device__ float g_up [4096 * 8192];   // up -> ffn_out
__device__ float g_sc [67108864];      // [B,H,S,S] scores / attn (256 MB)
__device__ float g_rm [1023];          // rel_pos row means

// ---------------- block reduction helper (blockDim == 256) ---------------
__device__ __forceinline__ float bred(float v, int op_max) {
    __shared__ float red[8];
    #pragma unroll
    for (int o = 16; o; o >>= 1) {
        float w = __shfl_xor_sync(0xffffffffu, v, o);
        v = op_max ? fmaxf(v, w) : v + w;
    }
    __syncthreads();
    if ((threadIdx.x & 31) == 0) red[threadIdx.x >> 5] = v;
    __syncthreads();
    v = red[threadIdx.x & 7];
    #pragma unroll
    for (int o = 4; o; o >>= 1) {
        float w = __shfl_xor_sync(0xffffffffu, v, o);
        v = op_max ? fmaxf(v, w) : v + w;
    }
    return v;
}

// ---------------- generic TF32 GEMM: C[M,N] = A[M,K] @ B[K,N] ------------
// 128x128 block tile, BK=32, 8 warps (2x4), double-buffered smem.
#define GLDA 40
#define GLDB 136
#define GASZ (128 * GLDA)
#define GBSZ (32 * GLDB)
#define GEMM_SMEM ((2 * GASZ + 2 * GBSZ) * 4)

__global__ void __launch_bounds__(256, 1) gemm_tf32(
    const float* __restrict__ A, const float* __restrict__ Bg,
    float* __restrict__ C, int M, int N, int K)
{
    extern __shared__ float sm[];
    float* As = sm;
    float* Bs = sm + 2 * GASZ;

    const int bm = blockIdx.y * 128;
    const int bn = blockIdx.x * 128;
    const int tid = threadIdx.x;
    const int warp = tid >> 5;
    const int wm = (warp >> 2) * 64;
    const int wn = (warp & 3) * 32;

    wmma::fragment<wmma::accumulator, 16, 16, 8, float> acc[4][2];
    #pragma unroll
    for (int i = 0; i < 4; i++)
        #pragma unroll
        for (int j = 0; j < 2; j++)
            wmma::fill_fragment(acc[i][j], 0.0f);

    const float* aP[4];
    const float* bP[4];
    int aOff[4], bOff[4];
    #pragma unroll
    for (int i = 0; i < 4; i++) {
        int idx = tid + 256 * i;
        int r = idx >> 3, c = (idx & 7) << 2;          // A tile 128x32
        aP[i] = A + (size_t)(bm + r) * K + c;
        aOff[i] = r * GLDA + c;
        int rb = idx >> 5, cb = (idx & 31) << 2;       // B tile 32x128
        bP[i] = Bg + (size_t)rb * N + bn + cb;
        bOff[i] = rb * GLDB + cb;
    }

    auto compute = [&](int buf) {
        const float* Ab = As + buf * GASZ;
        const float* Bb = Bs + buf * GBSZ;
        #pragma unroll
        for (int ks = 0; ks < 4; ks++) {
            wmma::fragment<wmma::matrix_a, 16, 16, 8, wmma::precision::tf32, wmma::row_major> af[4];
            wmma::fragment<wmma::matrix_b, 16, 16, 8, wmma::precision::tf32, wmma::row_major> bf[2];
            #pragma unroll
            for (int i = 0; i < 4; i++) {
                wmma::load_matrix_sync(af[i], Ab + (wm + i * 16) * GLDA + ks * 8, GLDA);
                #pragma unroll
                for (int t = 0; t < af[i].num_elements; t++)
                    af[i].x[t] = wmma::__float_to_tf32(af[i].x[t]);
            }
            #pragma unroll
            for (int j = 0; j < 2; j++) {
                wmma::load_matrix_sync(bf[j], Bb + (ks * 8) * GLDB + wn + j * 16, GLDB);
                #pragma unroll
                for (int t = 0; t < bf[j].num_elements; t++)
                    bf[j].x[t] = wmma::__float_to_tf32(bf[j].x[t]);
            }
            #pragma unroll
            for (int i = 0; i < 4; i++)
                #pragma unroll
                for (int j = 0; j < 2; j++)
                    wmma::mma_sync(acc[i][j], af[i], bf[j], acc[i][j]);
        }
    };

    // prologue: tile 0 -> buffer 0
    #pragma unroll
    for (int i = 0; i < 4; i++) {
        *(float4*)(As + aOff[i]) = *(const float4*)(aP[i]);
        *(float4*)(Bs + bOff[i]) = *(const float4*)(bP[i]);
    }
    __syncthreads();

    const int KT = K >> 5;
    for (int kt = 0; kt < KT - 1; kt++) {
        const int cur = kt & 1;
        float4 ra[4], rb[4];
        #pragma unroll
        for (int i = 0; i < 4; i++) {
            ra[i] = *(const float4*)(aP[i] + (kt + 1) * 32);
            rb[i] = *(const float4*)(bP[i] + (size_t)(kt + 1) * 32 * N);
        }
        compute(cur);
        #pragma unroll
        for (int i = 0; i < 4; i++) {
            *(float4*)(As + (cur ^ 1) * GASZ + aOff[i]) = ra[i];
            *(float4*)(Bs + (cur ^ 1) * GBSZ + bOff[i]) = rb[i];
        }
        __syncthreads();
    }
    compute((KT - 1) & 1);

    #pragma unroll
    for (int i = 0; i < 4; i++)
        #pragma unroll
        for (int j = 0; j < 2; j++)
            wmma::store_matrix_sync(C + (size_t)(bm + wm + i * 16) * N + (bn + wn + j * 16),
                                    acc[i][j], N, wmma::mem_row_major);
}

// ---------------- scores: per (b,h): S[q,k] = Q.K^T/8 + bias -------------
// Block: 128x128 output tile, K=64 fully resident. grid (4,4,256).
#define SC_SMEM (2 * 128 * 72 * 4)

__global__ void __launch_bounds__(256, 1) scores_k(
    const float* __restrict__ q, const float* __restrict__ k,
    const float* __restrict__ rm, float* __restrict__ sc)
{
    extern __shared__ float sm[];
    float* As = sm;             // [128][72]  q rows
    float* Bs = sm + 128 * 72;  // [128][72]  k rows (n-major; used col_major)
    const int bz = blockIdx.z;
    const int b = bz >> 5, h = bz & 31;
    const int bm = blockIdx.y * 128;
    const int bn = blockIdx.x * 128;
    const int tid = threadIdx.x, warp = tid >> 5;
    const int wm = (warp >> 2) * 64;
    const int wn = (warp & 3) * 32;

    const float* qb = q + ((size_t)b * 512) * 2048 + h * 64;
    const float* kb = k + ((size_t)b * 512) * 2048 + h * 64;

    #pragma unroll
    for (int i = 0; i < 8; i++) {
        int idx = tid + 256 * i;
        int r = idx >> 4, c = (idx & 15) << 2;
        *(float4*)(As + r * 72 + c) = *(const float4*)(qb + (size_t)(bm + r) * 2048 + c);
        *(float4*)(Bs + r * 72 + c) = *(const float4*)(kb + (size_t)(bn + r) * 2048 + c);
    }
    __syncthreads();

    wmma::fragment<wmma::accumulator, 16, 16, 8, float> acc[4][2];
    #pragma unroll
    for (int i = 0; i < 4; i++)
        #pragma unroll
        for (int j = 0; j < 2; j++)
            wmma::fill_fragment(acc[i][j], 0.0f);

    #pragma unroll
    for (int ks = 0; ks < 8; ks++) {
        wmma::fragment<wmma::matrix_a, 16, 16, 8, wmma::precision::tf32, wmma::row_major> af[4];
        wmma::fragment<wmma::matrix_b, 16, 16, 8, wmma::precision::tf32, wmma::col_major> bf[2];
        #pragma unroll
        for (int i = 0; i < 4; i++) {
            wmma::load_matrix_sync(af[i], As + (wm + i * 16) * 72 + ks * 8, 72);
            #pragma unroll
            for (int t = 0; t < af[i].num_elements; t++)
                af[i].x[t] = wmma::__float_to_tf32(af[i].x[t]);
        }
        #pragma unroll
        for (int j = 0; j < 2; j++) {
            wmma::load_matrix_sync(bf[j], Bs + (wn + j * 16) * 72 + ks * 8, 72);
            #pragma unroll
            for (int t = 0; t < bf[j].num_elements; t++)
                bf[j].x[t] = wmma::__float_to_tf32(bf[j].x[t]);
        }
        #pragma unroll
        for (int i = 0; i < 4; i++)
            #pragma unroll
            for (int j = 0; j < 2; j++)
                wmma::mma_sync(acc[i][j], af[i], bf[j], acc[i][j]);
    }
    __syncthreads();

    float* Cs = sm;  // [128][136] staging (reuses As/Bs)
    #pragma unroll
    for (int i = 0; i < 4; i++)
        #pragma unroll
        for (int j = 0; j < 2; j++)
            wmma::store_matrix_sync(Cs + (wm + i * 16) * 136 + (wn + j * 16),
                                    acc[i][j], 136, wmma::mem_row_major);
    __syncthreads();

    const size_t base = (size_t)bz * 262144;
    #pragma unroll
    for (int i = 0; i < 16; i++) {
        int idx = tid + 256 * i;
        int r = idx >> 5, c = (idx & 31) << 2;
        float4 vv = *(float4*)(Cs + r * 136 + c);
        int qi = bm + r, ki = bn + c;
        int o = ki - qi + 511;   // always in [0,1022]
        vv.x = vv.x * 0.125f + rm[o];
        vv.y = vv.y * 0.125f + rm[o + 1];
        vv.z = vv.z * 0.125f + rm[o + 2];
        vv.w = vv.w * 0.125f + rm[o + 3];
        *(float4*)(sc + base + (size_t)qi * 512 + ki) = vv;
    }
}

// ---------------- ctx: per (b,h): C[q,d] = attn[q,:] @ V[:,d] ------------
// M=512, N=64, K=512. Block 128x64 tile, BK=64. grid (4, 256).
#define CTX_SMEM ((128 * 72 + 64 * 72) * 4)

__global__ void __launch_bounds__(256, 1) ctx_k(
    const float* __restrict__ attn, const float* __restrict__ v,
    float* __restrict__ ctx)
{
    extern __shared__ float sm[];
    float* As = sm;            // [128][72]
    float* Bs = sm + 128 * 72; // [64][72]
    const int bz = blockIdx.y;
    const int b = bz >> 5, h = bz & 31;
    const int bm = blockIdx.x * 128;
    const int tid = threadIdx.x, warp = tid >> 5;
    const int wm = (warp >> 1) * 32;
    const int wn = (warp & 1) * 32;

    const float* ab = attn + (size_t)bz * 262144;
    const float* vb = v + ((size_t)b * 512) * 2048 + h * 64;

    wmma::fragment<wmma::accumulator, 16, 16, 8, float> acc[2][2];
    #pragma unroll
    for (int i = 0; i < 2; i++)
        #pragma unroll
        for (int j = 0; j < 2; j++)
            wmma::fill_fragment(acc[i][j], 0.0f);

    for (int kt = 0; kt < 8; kt++) {
        int k0 = kt * 64;
        #pragma unroll
        for (int i = 0; i < 8; i++) {
            int idx = tid + 256 * i;
            int r = idx >> 4, c = (idx & 15) << 2;
            *(float4*)(As + r * 72 + c) =
                *(const float4*)(ab + (size_t)(bm + r) * 512 + k0 + c);
        }
        #pragma unroll
        for (int i = 0; i < 4; i++) {
            int idx = tid + 256 * i;
            int r = idx >> 4, c = (idx & 15) << 2;
            *(float4*)(Bs + r * 72 + c) =
                *(const float4*)(vb + (size_t)(k0 + r) * 2048 + c);
        }
        __syncthreads();
        #pragma unroll
        for (int ks = 0; ks < 8; ks++) {
            wmma::fragment<wmma::matrix_a, 16, 16, 8, wmma::precision::tf32, wmma::row_major> af[2];
            wmma::fragment<wmma::matrix_b, 16, 16, 8, wmma::precision::tf32, wmma::row_major> bf[2];
            #pragma unroll
            for (int i = 0; i < 2; i++) {
                wmma::load_matrix_sync(af[i], As + (wm + i * 16) * 72 + ks * 8, 72);
                #pragma unroll
                for (int t = 0; t < af[i].num_elements; t++)
                    af[i].x[t] = wmma::__float_to_tf32(af[i].x[t]);
            }
            #pragma unroll
            for (int j = 0; j < 2; j++) {
                wmma::load_matrix_sync(bf[j], Bs + (ks * 8) * 72 + wn + j * 16, 72);
                #pragma unroll
                for (int t = 0; t < bf[j].num_elements; t++)
                    bf[j].x[t] = wmma::__float_to_tf32(bf[j].x[t]);
            }
            #pragma unroll
            for (int i = 0; i < 2; i++)
                #pragma unroll
                for (int j = 0; j < 2; j++)
                    wmma::mma_sync(acc[i][j], af[i], bf[j], acc[i][j]);
        }
        __syncthreads();
    }

    float* cb = ctx + ((size_t)b * 512 + bm) * 2048 + h * 64;
    #pragma unroll
    for (int i = 0; i < 2; i++)
        #pragma unroll
        for (int j = 0; j < 2; j++)
            wmma::store_matrix_sync(cb + (size_t)(wm + i * 16) * 2048 + wn + j * 16,
                                    acc[i][j], 2048, wmma::mem_row_major);
}

// ---------------- softmax over rows of 512 -------------------------------
__global__ void __launch_bounds__(256) softmax_k(float* __restrict__ sc) {
    float* p = sc + (size_t)blockIdx.x * 512;
    int t = threadIdx.x;
    float2 v = ((float2*)p)[t];
    float m = bred(fmaxf(v.x, v.y), 1);
    float e0 = __expf(v.x - m), e1 = __expf(v.y - m);
    float inv = 1.0f / bred(e0 + e1, 0);
    ((float2*)p)[t] = make_float2(e0 * inv, e1 * inv);
}

// ---------------- residual add + layernorm (row = 2048) ------------------
__global__ void __launch_bounds__(256) add_ln_k(
    const float* __restrict__ xr, const float* __restrict__ yr,
    const float* __restrict__ g, const float* __restrict__ bt,
    float* __restrict__ out)
{
    size_t row = blockIdx.x;
    const float4* xp = (const float4*)(xr + row * 2048);
    const float4* yp = (const float4*)(yr + row * 2048);
    int t = threadIdx.x;
    float v[8];
    #pragma unroll
    for (int i = 0; i < 2; i++) {
        float4 a = xp[t + 256 * i];
        float4 c = yp[t + 256 * i];
        v[4 * i + 0] = a.x + c.x; v[4 * i + 1] = a.y + c.y;
        v[4 * i + 2] = a.z + c.z; v[4 * i + 3] = a.w + c.w;
    }
    float s = 0.0f;
    #pragma unroll
    for (int i = 0; i < 8; i++) s += v[i];
    float mu = bred(s, 0) * (1.0f / 2048.0f);
    float qs = 0.0f;
    #pragma unroll
    for (int i = 0; i < 8; i++) { float d = v[i] - mu; qs += d * d; }
    float rstd = rsqrtf(bred(qs, 0) * (1.0f / 2048.0f) + 1e-6f);
    float4* op = (float4*)(out + row * 2048);
    #pragma unroll
    for (int i = 0; i < 2; i++) {
        int c4 = t + 256 * i;
        float4 gv = ((const float4*)g)[c4];
        float4 bv = ((const float4*)bt)[c4];
        float4 o;
        o.x = (v[4 * i + 0] - mu) * rstd * gv.x + bv.x;
        o.y = (v[4 * i + 1] - mu) * rstd * gv.y + bv.y;
        o.z = (v[4 * i + 2] - mu) * rstd * gv.z + bv.z;
        o.w = (v[4 * i + 3] - mu) * rstd * gv.w + bv.w;
        op[c4] = o;
    }
}

// ---------------- silu(gate)*up, in place into gate ----------------------
__global__ void __launch_bounds__(256) silu_mul_k(
    float* __restrict__ gate, const float* __restrict__ up)
{
    size_t i = (size_t)blockIdx.x * 256 + threadIdx.x;
    float4 gv = ((float4*)gate)[i];
    float4 uv = ((const float4*)up)[i];
    gv.x = gv.x / (1.0f + __expf(-gv.x)) * uv.x;
    gv.y = gv.y / (1.0f + __expf(-gv.y)) * uv.y;
    gv.z = gv.z / (1.0f + __expf(-gv.z)) * uv.z;
    gv.w = gv.w / (1.0f + __expf(-gv.w)) * uv.w;
    ((float4*)gate)[i] = gv;
}

// ---------------- rel_pos row means ---------------------------------------
__global__ void rowmean_k(const float* __restrict__ rel, float* __restrict__ rm) {
    int r = blockIdx.x * 256 + threadIdx.x;
    if (r < 1023) {
        float s = 0.0f;
        #pragma unroll
        for (int d = 0; d < 64; d++) s += rel[r * 64 + d];
        rm[r] = s * (1.0f / 64.0f);
    }
}

// ---------------- host launcher -------------------------------------------
extern "C" void kernel_launch(void* const* d_in, const int* in_sizes, int n_in,
                              void* d_out, int out_size)
{
    (void)in_sizes; (void)n_in; (void)out_size;
    const float* x    = (const float*)d_in[0];
    const float* wq   = (const float*)d_in[1];
    const float* wk   = (const float*)d_in[2];
    const float* wv   = (const float*)d_in[3];
    const float* wo   = (const float*)d_in[4];
    const float* rel  = (const float*)d_in[5];
    const float* ln1g = (const float*)d_in[6];
    const float* ln1b = (const float*)d_in[7];
    const float* gw   = (const float*)d_in[8];
    const float* uw   = (const float*)d_in[9];
    const float* dw   = (const float*)d_in[10];
    const float* ln2g = (const float*)d_in[11];
    const float* ln2b = (const float*)d_in[12];
    float* out = (float*)d_out;

    float *q, *k, *v, *ctx, *h1, *tmp, *up, *sc, *rm;
    cudaGetSymbolAddress((void**)&q,   g_q);
    cudaGetSymbolAddress((void**)&k,   g_k);
    cudaGetSymbolAddress((void**)&v,   g_v);
    cudaGetSymbolAddress((void**)&ctx, g_ctx);
    cudaGetSymbolAddress((void**)&h1,  g_h1);
    cudaGetSymbolAddress((void**)&tmp, g_tmp);
    cudaGetSymbolAddress((void**)&up,  g_up);
    cudaGetSymbolAddress((void**)&sc,  g_sc);
    cudaGetSymbolAddress((void**)&rm,  g_rm);

    cudaFuncSetAttribute(gemm_tf32, cudaFuncAttributeMaxDynamicSharedMemorySize, GEMM_SMEM);
    cudaFuncSetAttribute(scores_k,  cudaFuncAttributeMaxDynamicSharedMemorySize, SC_SMEM);
    cudaFuncSetAttribute(ctx_k,     cudaFuncAttributeMaxDynamicSharedMemorySize, CTX_SMEM);

    // bias rowmeans
    rowmean_k<<<4, 256>>>(rel, rm);

    // QKV projections: [4096,2048] x [2048,2048]
    gemm_tf32<<<dim3(16, 32), 256, GEMM_SMEM>>>(x, wq, q, 4096, 2048, 2048);
    gemm_tf32<<<dim3(16, 32), 256, GEMM_SMEM>>>(x, wk, k, 4096, 2048, 2048);
    gemm_tf32<<<dim3(16, 32), 256, GEMM_SMEM>>>(x, wv, v, 4096, 2048, 2048);

    // attention
    scores_k<<<dim3(4, 4, 256), 256, SC_SMEM>>>(q, k, rm, sc);
    softmax_k<<<131072, 256>>>(sc);
    ctx_k<<<dim3(4, 256), 256, CTX_SMEM>>>(sc, v, ctx);

    // output projection + residual + LN1
    gemm_tf32<<<dim3(16, 32), 256, GEMM_SMEM>>>(ctx, wo, tmp, 4096, 2048, 2048);
    add_ln_k<<<4096, 256>>>(x, tmp, ln1g, ln1b, h1);

    // FFN (SwiGLU)
    gemm_tf32<<<dim3(64, 32), 256, GEMM_SMEM>>>(h1, gw, tmp, 4096, 8192, 2048);
    gemm_tf32<<<dim3(64, 32), 256, GEMM_SMEM>>>(h1, uw, up,  4096, 8192, 2048);
    silu_mul_k<<<32768, 256>>>(tmp, up);                       // tmp = silu(gate)*up
    gemm_tf32<<<dim3(16, 32), 256, GEMM_SMEM>>>(tmp, dw, up, 4096, 2048, 8192);

    // residual + LN2 -> output
    add_ln_k<<<4096, 256>>>(h1, up, ln2g, ln2b, out);
}

// round 3
// speedup vs baseline: 3.5903x; 3.5903x over previous
#include <cuda_runtime.h>
#include <mma.h>
#include <cstdint>

using namespace nvcuda;
typedef __half half_t;

// Problem dims: B=8, S=512, D=2048, H=32, HD=64, I=8192, NT=4096 tokens.

// ---------------- scratch (device globals; no allocation allowed) --------
__device__ float  g_sc [67108864];       // [B,H,S,S] fp32 scores (256 MB)
__device__ float  g_tmp[4096 * 8192];    // attn_out / gate (fp32)
__device__ float  g_up [4096 * 8192];    // up / ffn_out (fp32)
__device__ float  g_h1 [4096 * 2048];    // post-LN1 (fp32)
__device__ float  g_rm [1023];           // rel_pos row means
// fp16 operands
__device__ half_t g_xh  [4096 * 2048];
__device__ half_t g_qh  [4096 * 2048];
__device__ half_t g_kh  [4096 * 2048];
__device__ half_t g_vh  [4096 * 2048];
__device__ half_t g_ctxh[4096 * 2048];
__device__ half_t g_h1h [4096 * 2048];
__device__ half_t g_acth[4096 * 8192];
__device__ half_t g_att [67108864];      // fp16 attn probs (128 MB)
__device__ half_t g_wqh[2048 * 2048];
__device__ half_t g_wkh[2048 * 2048];
__device__ half_t g_wvh[2048 * 2048];
__device__ half_t g_woh[2048 * 2048];
__device__ half_t g_gwh[2048 * 8192];
__device__ half_t g_uwh[2048 * 8192];
__device__ half_t g_dwh[8192 * 2048];

// ---------------- small helpers ------------------------------------------
__device__ __forceinline__ uint32_t smem_u32(const void* p) {
    uint32_t a;
    asm("{ .reg .u64 t; cvta.to.shared.u64 t, %1; cvt.u32.u64 %0, t; }"
        : "=r"(a) : "l"(p));
    return a;
}
__device__ __forceinline__ void cpa16(uint32_t dst, const void* src) {
    asm volatile("cp.async.cg.shared.global [%0], [%1], 16;"
                 :: "r"(dst), "l"(src) : "memory");
}
__device__ __forceinline__ void cpa_commit() {
    asm volatile("cp.async.commit_group;" ::: "memory");
}
template <int N>
__device__ __forceinline__ void cpa_wait() {
    asm volatile("cp.async.wait_group %0;" :: "n"(N) : "memory");
}

__device__ __forceinline__ float bred(float v, int op_max) {
    __shared__ float red[8];
    #pragma unroll
    for (int o = 16; o; o >>= 1) {
        float w = __shfl_xor_sync(0xffffffffu, v, o);
        v = op_max ? fmaxf(v, w) : v + w;
    }
    __syncthreads();
    if ((threadIdx.x & 31) == 0) red[threadIdx.x >> 5] = v;
    __syncthreads();
    v = red[threadIdx.x & 7];
    #pragma unroll
    for (int o = 4; o; o >>= 1) {
        float w = __shfl_xor_sync(0xffffffffu, v, o);
        v = op_max ? fmaxf(v, w) : v + w;
    }
    return v;
}

// =================== fp16 GEMM: C[M,N] = A[M,K] @ B[K,N] ==================
// Tile 128x128, BK=32, 4-stage cp.async pipeline, 8 warps (2x4), warptile 64x32.
#define LDA 40
#define LDB 136
#define A_STG 10240                       // 128*40*2 bytes
#define B_STG 8704                        // 32*136*2 bytes
#define B_BASE 40960                      // 4*A_STG
#define GH_SMEM 75776                     // B_BASE + 4*B_STG
#define LDC 132                           // epilogue staging (floats)

template <typename OutT>
__global__ void __launch_bounds__(256, 1) gemm_h(
    const half_t* __restrict__ A, const half_t* __restrict__ B,
    OutT* __restrict__ C, int M, int N, int K)
{
    extern __shared__ __align__(128) char smem[];
    const uint32_t sb = smem_u32(smem);
    const int tid = threadIdx.x;
    const int warp = tid >> 5;
    const int bm = blockIdx.y * 128, bn = blockIdx.x * 128;
    const int wm = (warp >> 2) * 64, wn = (warp & 3) * 32;

    // per-thread copy chunk coordinates (2 chunks of 16B for A, 2 for B)
    const int ar0 = tid >> 2,            ac0 = (tid & 3) << 3;
    const int ar1 = (tid + 256) >> 2,    ac1 = ((tid + 256) & 3) << 3;
    const int br0 = tid >> 4,            bc0 = (tid & 15) << 3;
    const int br1 = (tid + 256) >> 4,    bc1 = ((tid + 256) & 15) << 3;

    const half_t* Abm = A + (size_t)bm * K;
    const half_t* Bbn = B + bn;

    auto load_stage = [&](int s, int kt) {
        const int k0 = kt * 32;
        uint32_t aB = sb + s * A_STG;
        uint32_t bB = sb + B_BASE + s * B_STG;
        cpa16(aB + (ar0 * LDA + ac0) * 2, Abm + (size_t)ar0 * K + k0 + ac0);
        cpa16(aB + (ar1 * LDA + ac1) * 2, Abm + (size_t)ar1 * K + k0 + ac1);
        cpa16(bB + (br0 * LDB + bc0) * 2, Bbn + (size_t)(k0 + br0) * N + bc0);
        cpa16(bB + (br1 * LDB + bc1) * 2, Bbn + (size_t)(k0 + br1) * N + bc1);
    };

    wmma::fragment<wmma::accumulator, 16, 16, 16, float> acc[4][2];
    #pragma unroll
    for (int i = 0; i < 4; i++)
        #pragma unroll
        for (int j = 0; j < 2; j++)
            wmma::fill_fragment(acc[i][j], 0.0f);

    const int KT = K >> 5;
    #pragma unroll
    for (int s = 0; s < 3; s++) { load_stage(s, s); cpa_commit(); }

    for (int kt = 0; kt < KT; kt++) {
        if (kt + 3 < KT) load_stage((kt + 3) & 3, kt + 3);
        cpa_commit();
        cpa_wait<3>();
        __syncthreads();

        const int s = kt & 3;
        const half_t* As = (const half_t*)(smem + s * A_STG);
        const half_t* Bs = (const half_t*)(smem + B_BASE + s * B_STG);
        #pragma unroll
        for (int ks = 0; ks < 2; ks++) {
            wmma::fragment<wmma::matrix_a, 16, 16, 16, half_t, wmma::row_major> af[4];
            wmma::fragment<wmma::matrix_b, 16, 16, 16, half_t, wmma::row_major> bf[2];
            #pragma unroll
            for (int i = 0; i < 4; i++)
                wmma::load_matrix_sync(af[i], As + (wm + i * 16) * LDA + ks * 16, LDA);
            #pragma unroll
            for (int j = 0; j < 2; j++)
                wmma::load_matrix_sync(bf[j], Bs + (ks * 16) * LDB + wn + j * 16, LDB);
            #pragma unroll
            for (int i = 0; i < 4; i++)
                #pragma unroll
                for (int j = 0; j < 2; j++)
                    wmma::mma_sync(acc[i][j], af[i], bf[j], acc[i][j]);
        }
        __syncthreads();
    }

    // epilogue via fp32 smem staging
    float* Cs = (float*)smem;
    #pragma unroll
    for (int i = 0; i < 4; i++)
        #pragma unroll
        for (int j = 0; j < 2; j++)
            wmma::store_matrix_sync(Cs + (wm + i * 16) * LDC + wn + j * 16,
                                    acc[i][j], LDC, wmma::mem_row_major);
    __syncthreads();

    #pragma unroll
    for (int it = 0; it < 16; it++) {
        int idx = tid + 256 * it;
        int r = idx >> 5, c = (idx & 31) << 2;
        float4 v = *(float4*)(Cs + r * LDC + c);
        if constexpr (sizeof(OutT) == 4) {
            *(float4*)((float*)C + (size_t)(bm + r) * N + bn + c) = v;
        } else {
            half2 h0 = __floats2half2_rn(v.x, v.y);
            half2 h1 = __floats2half2_rn(v.z, v.w);
            uint2 pk = make_uint2(*(uint32_t*)&h0, *(uint32_t*)&h1);
            *(uint2*)((half_t*)C + (size_t)(bm + r) * N + bn + c) = pk;
        }
    }
}

// =================== scores: S[q,k] = QK^T/8 + bias (fp16 mma) ============
#define SC_SMEM 69632   // staging 128x136 floats dominates

__global__ void __launch_bounds__(256, 1) scores_k(
    const half_t* __restrict__ q, const half_t* __restrict__ k,
    const float* __restrict__ rm, float* __restrict__ sc)
{
    extern __shared__ __align__(128) char smem[];
    half_t* As = (half_t*)smem;                 // [128][72]
    half_t* Bs = (half_t*)smem + 128 * 72;      // [128][72]
    const int bz = blockIdx.z;
    const int b = bz >> 5, h = bz & 31;
    const int bm = blockIdx.y * 128, bn = blockIdx.x * 128;
    const int tid = threadIdx.x, warp = tid >> 5;
    const int wm = (warp >> 2) * 64, wn = (warp & 3) * 32;

    const half_t* qb = q + ((size_t)b * 512 + bm) * 2048 + h * 64;
    const half_t* kb = k + ((size_t)b * 512 + bn) * 2048 + h * 64;

    #pragma unroll
    for (int i = 0; i < 4; i++) {
        int idx = tid + 256 * i;
        int r = idx >> 3, c = (idx & 7) << 3;
        *(uint4*)(As + r * 72 + c) = *(const uint4*)(qb + (size_t)r * 2048 + c);
        *(uint4*)(Bs + r * 72 + c) = *(const uint4*)(kb + (size_t)r * 2048 + c);
    }
    __syncthreads();

    wmma::fragment<wmma::accumulator, 16, 16, 16, float> acc[4][2];
    #pragma unroll
    for (int i = 0; i < 4; i++)
        #pragma unroll
        for (int j = 0; j < 2; j++)
            wmma::fill_fragment(acc[i][j], 0.0f);

    #pragma unroll
    for (int ks = 0; ks < 4; ks++) {
        wmma::fragment<wmma::matrix_a, 16, 16, 16, half_t, wmma::row_major> af[4];
        wmma::fragment<wmma::matrix_b, 16, 16, 16, half_t, wmma::col_major> bf[2];
        #pragma unroll
        for (int i = 0; i < 4; i++)
            wmma::load_matrix_sync(af[i], As + (wm + i * 16) * 72 + ks * 16, 72);
        #pragma unroll
        for (int j = 0; j < 2; j++)
            wmma::load_matrix_sync(bf[j], Bs + (wn + j * 16) * 72 + ks * 16, 72);
        #pragma unroll
        for (int i = 0; i < 4; i++)
            #pragma unroll
            for (int j = 0; j < 2; j++)
                wmma::mma_sync(acc[i][j], af[i], bf[j], acc[i][j]);
    }
    __syncthreads();

    float* Cs = (float*)smem;  // [128][136]
    #pragma unroll
    for (int i = 0; i < 4; i++)
        #pragma unroll
        for (int j = 0; j < 2; j++)
            wmma::store_matrix_sync(Cs + (wm + i * 16) * 136 + (wn + j * 16),
                                    acc[i][j], 136, wmma::mem_row_major);
    __syncthreads();

    const size_t base = (size_t)bz * 262144;
    #pragma unroll
    for (int i = 0; i < 16; i++) {
        int idx = tid + 256 * i;
        int r = idx >> 5, c = (idx & 31) << 2;
        float4 vv = *(float4*)(Cs + r * 136 + c);
        int qi = bm + r, ki = bn + c;
        int o = ki - qi + 511;
        vv.x = vv.x * 0.125f + rm[o];
        vv.y = vv.y * 0.125f + rm[o + 1];
        vv.z = vv.z * 0.125f + rm[o + 2];
        vv.w = vv.w * 0.125f + rm[o + 3];
        *(float4*)(sc + base + (size_t)qi * 512 + ki) = vv;
    }
}

// =================== ctx: C[q,d] = P[q,:] @ V[:,d] (fp16 mma) ==============
#define CTX_SMEM 36864  // staging 128x72 floats dominates

__global__ void __launch_bounds__(256, 1) ctx_k(
    const half_t* __restrict__ att, const half_t* __restrict__ v,
    half_t* __restrict__ ctx)
{
    extern __shared__ __align__(128) char smem[];
    half_t* As = (half_t*)smem;                 // [128][72]
    half_t* Bs = (half_t*)smem + 128 * 72;      // [64][72]
    const int bz = blockIdx.y;
    const int b = bz >> 5, h = bz & 31;
    const int bm = blockIdx.x * 128;
    const int tid = threadIdx.x, warp = tid >> 5;
    const int wm = (warp >> 1) * 32, wn = (warp & 1) * 32;

    const half_t* ab = att + (size_t)bz * 262144 + (size_t)bm * 512;
    const half_t* vb = v + ((size_t)b * 512) * 2048 + h * 64;

    wmma::fragment<wmma::accumulator, 16, 16, 16, float> acc[2][2];
    #pragma unroll
    for (int i = 0; i < 2; i++)
        #pragma unroll
        for (int j = 0; j < 2; j++)
            wmma::fill_fragment(acc[i][j], 0.0f);

    for (int kt = 0; kt < 8; kt++) {
        int k0 = kt * 64;
        #pragma unroll
        for (int i = 0; i < 4; i++) {
            int idx = tid + 256 * i;
            int r = idx >> 3, c = (idx & 7) << 3;
            *(uint4*)(As + r * 72 + c) = *(const uint4*)(ab + (size_t)r * 512 + k0 + c);
        }
        #pragma unroll
        for (int i = 0; i < 2; i++) {
            int idx = tid + 256 * i;
            int r = idx >> 3, c = (idx & 7) << 3;
            *(uint4*)(Bs + r * 72 + c) = *(const uint4*)(vb + (size_t)(k0 + r) * 2048 + c);
        }
        __syncthreads();
        #pragma unroll
        for (int ks = 0; ks < 4; ks++) {
            wmma::fragment<wmma::matrix_a, 16, 16, 16, half_t, wmma::row_major> af[2];
            wmma::fragment<wmma::matrix_b, 16, 16, 16, half_t, wmma::row_major> bf[2];
            #pragma unroll
            for (int i = 0; i < 2; i++)
                wmma::load_matrix_sync(af[i], As + (wm + i * 16) * 72 + ks * 16, 72);
            #pragma unroll
            for (int j = 0; j < 2; j++)
                wmma::load_matrix_sync(bf[j], Bs + (ks * 16) * 72 + wn + j * 16, 72);
            #pragma unroll
            for (int i = 0; i < 2; i++)
                #pragma unroll
                for (int j = 0; j < 2; j++)
                    wmma::mma_sync(acc[i][j], af[i], bf[j], acc[i][j]);
        }
        __syncthreads();
    }

    float* Cs = (float*)smem;  // [128][72]
    #pragma unroll
    for (int i = 0; i < 2; i++)
        #pragma unroll
        for (int j = 0; j < 2; j++)
            wmma::store_matrix_sync(Cs + (wm + i * 16) * 72 + wn + j * 16,
                                    acc[i][j], 72, wmma::mem_row_major);
    __syncthreads();

    half_t* cb = ctx + ((size_t)b * 512 + bm) * 2048 + h * 64;
    #pragma unroll
    for (int i = 0; i < 8; i++) {
        int idx = tid + 256 * i;
        int r = idx >> 4, c = (idx & 15) << 2;
        float4 vv = *(float4*)(Cs + r * 72 + c);
        half2 h0 = __floats2half2_rn(vv.x, vv.y);
        half2 h1 = __floats2half2_rn(vv.z, vv.w);
        *(uint2*)(cb + (size_t)r * 2048 + c) =
            make_uint2(*(uint32_t*)&h0, *(uint32_t*)&h1);
    }
}

// ---------------- softmax over rows of 512 (fp32 in -> fp16 probs) -------
__global__ void __launch_bounds__(256) softmax_k(
    const float* __restrict__ sc, half_t* __restrict__ att)
{
    const float* p = sc + (size_t)blockIdx.x * 512;
    half_t* o = att + (size_t)blockIdx.x * 512;
    int t = threadIdx.x;
    float2 v = ((const float2*)p)[t];
    float m = bred(fmaxf(v.x, v.y), 1);
    float e0 = __expf(v.x - m), e1 = __expf(v.y - m);
    float inv = 1.0f / bred(e0 + e1, 0);
    half2 hv = __floats2half2_rn(e0 * inv, e1 * inv);
    ((half2*)o)[t] = hv;
}

// ---------------- residual add + layernorm (row = 2048) ------------------
__global__ void __launch_bounds__(256) add_ln_k(
    const float* __restrict__ xr, const float* __restrict__ yr,
    const float* __restrict__ g, const float* __restrict__ bt,
    float* __restrict__ out, half_t* __restrict__ hout)
{
    size_t row = blockIdx.x;
    const float4* xp = (const float4*)(xr + row * 2048);
    const float4* yp = (const float4*)(yr + row * 2048);
    int t = threadIdx.x;
    float v[8];
    #pragma unroll
    for (int i = 0; i < 2; i++) {
        float4 a = xp[t + 256 * i];
        float4 c = yp[t + 256 * i];
        v[4 * i + 0] = a.x + c.x; v[4 * i + 1] = a.y + c.y;
        v[4 * i + 2] = a.z + c.z; v[4 * i + 3] = a.w + c.w;
    }
    float s = 0.0f;
    #pragma unroll
    for (int i = 0; i < 8; i++) s += v[i];
    float mu = bred(s, 0) * (1.0f / 2048.0f);
    float qs = 0.0f;
    #pragma unroll
    for (int i = 0; i < 8; i++) { float d = v[i] - mu; qs += d * d; }
    float rstd = rsqrtf(bred(qs, 0) * (1.0f / 2048.0f) + 1e-6f);
    float4* op = (float4*)(out + row * 2048);
    #pragma unroll
    for (int i = 0; i < 2; i++) {
        int c4 = t + 256 * i;
        float4 gv = ((const float4*)g)[c4];
        float4 bv = ((const float4*)bt)[c4];
        float4 o;
        o.x = (v[4 * i + 0] - mu) * rstd * gv.x + bv.x;
        o.y = (v[4 * i + 1] - mu) * rstd * gv.y + bv.y;
        o.z = (v[4 * i + 2] - mu) * rstd * gv.z + bv.z;
        o.w = (v[4 * i + 3] - mu) * rstd * gv.w + bv.w;
        op[c4] = o;
        if (hout) {
            half2 h0 = __floats2half2_rn(o.x, o.y);
            half2 h1 = __floats2half2_rn(o.z, o.w);
            *(uint2*)(hout + row * 2048 + c4 * 4) =
                make_uint2(*(uint32_t*)&h0, *(uint32_t*)&h1);
        }
    }
}

// ---------------- silu(gate)*up -> fp16 act --------------------------------
__global__ void __launch_bounds__(256) silu_mul_k(
    const float* __restrict__ gate, const float* __restrict__ up,
    half_t* __restrict__ act)
{
    size_t i = (size_t)blockIdx.x * 256 + threadIdx.x;
    float4 gv = ((const float4*)gate)[i];
    float4 uv = ((const float4*)up)[i];
    float4 r;
    r.x = gv.x / (1.0f + __expf(-gv.x)) * uv.x;
    r.y = gv.y / (1.0f + __expf(-gv.y)) * uv.y;
    r.z = gv.z / (1.0f + __expf(-gv.z)) * uv.z;
    r.w = gv.w / (1.0f + __expf(-gv.w)) * uv.w;
    half2 h0 = __floats2half2_rn(r.x, r.y);
    half2 h1 = __floats2half2_rn(r.z, r.w);
    ((uint2*)act)[i] = make_uint2(*(uint32_t*)&h0, *(uint32_t*)&h1);
}

// ---------------- float -> half conversion (8 elems/thread) ---------------
__global__ void __launch_bounds__(256) f2h_k(
    const float* __restrict__ in, half_t* __restrict__ out)
{
    size_t i = ((size_t)blockIdx.x * 256 + threadIdx.x) * 8;
    float4 a = *(const float4*)(in + i);
    float4 b = *(const float4*)(in + i + 4);
    half2 h0 = __floats2half2_rn(a.x, a.y);
    half2 h1 = __floats2half2_rn(a.z, a.w);
    half2 h2 = __floats2half2_rn(b.x, b.y);
    half2 h3 = __floats2half2_rn(b.z, b.w);
    uint4 pk = make_uint4(*(uint32_t*)&h0, *(uint32_t*)&h1,
                          *(uint32_t*)&h2, *(uint32_t*)&h3);
    *(uint4*)(out + i) = pk;
}

// ---------------- rel_pos row means ---------------------------------------
__global__ void rowmean_k(const float* __restrict__ rel, float* __restrict__ rm) {
    int r = blockIdx.x * 256 + threadIdx.x;
    if (r < 1023) {
        float s = 0.0f;
        #pragma unroll
        for (int d = 0; d < 64; d++) s += rel[r * 64 + d];
        rm[r] = s * (1.0f / 64.0f);
    }
}

// =================== host side ============================================
extern "C" void kernel_launch(void* const* d_in, const int* in_sizes, int n_in,
                              void* d_out, int out_size)
{
    (void)in_sizes; (void)n_in; (void)out_size;
    const float* x    = (const float*)d_in[0];
    const float* wq   = (const float*)d_in[1];
    const float* wk   = (const float*)d_in[2];
    const float* wv   = (const float*)d_in[3];
    const float* wo   = (const float*)d_in[4];
    const float* rel  = (const float*)d_in[5];
    const float* ln1g = (const float*)d_in[6];
    const float* ln1b = (const float*)d_in[7];
    const float* gw   = (const float*)d_in[8];
    const float* uw   = (const float*)d_in[9];
    const float* dw   = (const float*)d_in[10];
    const float* ln2g = (const float*)d_in[11];
    const float* ln2b = (const float*)d_in[12];
    float* out = (float*)d_out;

    float *sc, *tmp, *up, *h1, *rm;
    half_t *xh, *qh, *kh, *vh, *ctxh, *h1h, *acth, *att;
    half_t *wqh, *wkh, *wvh, *woh, *gwh, *uwh, *dwh;
    cudaGetSymbolAddress((void**)&sc,   g_sc);
    cudaGetSymbolAddress((void**)&tmp,  g_tmp);
    cudaGetSymbolAddress((void**)&up,   g_up);
    cudaGetSymbolAddress((void**)&h1,   g_h1);
    cudaGetSymbolAddress((void**)&rm,   g_rm);
    cudaGetSymbolAddress((void**)&xh,   g_xh);
    cudaGetSymbolAddress((void**)&qh,   g_qh);
    cudaGetSymbolAddress((void**)&kh,   g_kh);
    cudaGetSymbolAddress((void**)&vh,   g_vh);
    cudaGetSymbolAddress((void**)&ctxh, g_ctxh);
    cudaGetSymbolAddress((void**)&h1h,  g_h1h);
    cudaGetSymbolAddress((void**)&acth, g_acth);
    cudaGetSymbolAddress((void**)&att,  g_att);
    cudaGetSymbolAddress((void**)&wqh,  g_wqh);
    cudaGetSymbolAddress((void**)&wkh,  g_wkh);
    cudaGetSymbolAddress((void**)&wvh,  g_wvh);
    cudaGetSymbolAddress((void**)&woh,  g_woh);
    cudaGetSymbolAddress((void**)&gwh,  g_gwh);
    cudaGetSymbolAddress((void**)&uwh,  g_uwh);
    cudaGetSymbolAddress((void**)&dwh,  g_dwh);

    cudaFuncSetAttribute(gemm_h<float>,  cudaFuncAttributeMaxDynamicSharedMemorySize, GH_SMEM);
    cudaFuncSetAttribute(gemm_h<half_t>, cudaFuncAttributeMaxDynamicSharedMemorySize, GH_SMEM);
    cudaFuncSetAttribute(scores_k, cudaFuncAttributeMaxDynamicSharedMemorySize, SC_SMEM);
    cudaFuncSetAttribute(ctx_k,    cudaFuncAttributeMaxDynamicSharedMemorySize, CTX_SMEM);

    // fp16 conversions (weights + input)
    f2h_k<<<4096, 256>>>(x,  xh);
    f2h_k<<<2048, 256>>>(wq, wqh);
    f2h_k<<<2048, 256>>>(wk, wkh);
    f2h_k<<<2048, 256>>>(wv, wvh);
    f2h_k<<<2048, 256>>>(wo, woh);
    f2h_k<<<8192, 256>>>(gw, gwh);
    f2h_k<<<8192, 256>>>(uw, uwh);
    f2h_k<<<8192, 256>>>(dw, dwh);
    rowmean_k<<<4, 256>>>(rel, rm);

    // QKV projections -> fp16
    gemm_h<half_t><<<dim3(16, 32), 256, GH_SMEM>>>(xh, wqh, qh, 4096, 2048, 2048);
    gemm_h<half_t><<<dim3(16, 32), 256, GH_SMEM>>>(xh, wkh, kh, 4096, 2048, 2048);
    gemm_h<half_t><<<dim3(16, 32), 256, GH_SMEM>>>(xh, wvh, vh, 4096, 2048, 2048);

    // attention
    scores_k<<<dim3(4, 4, 256), 256, SC_SMEM>>>(qh, kh, rm, sc);
    softmax_k<<<131072, 256>>>(sc, att);
    ctx_k<<<dim3(4, 256), 256, CTX_SMEM>>>(att, vh, ctxh);

    // output projection + residual + LN1
    gemm_h<float><<<dim3(16, 32), 256, GH_SMEM>>>(ctxh, woh, tmp, 4096, 2048, 2048);
    add_ln_k<<<4096, 256>>>(x, tmp, ln1g, ln1b, h1, h1h);

    // FFN (SwiGLU)
    gemm_h<float><<<dim3(64, 32), 256, GH_SMEM>>>(h1h, gwh, tmp, 4096, 8192, 2048);
    gemm_h<float><<<dim3(64, 32), 256, GH_SMEM>>>(h1h, uwh, up,  4096, 8192, 2048);
    silu_mul_k<<<32768, 256>>>(tmp, up, acth);
    gemm_h<float><<<dim3(16, 32), 256, GH_SMEM>>>(acth, dwh, up, 4096, 2048, 8192);

    // residual + LN2 -> output
    add_ln_k<<<4096, 256>>>(h1, up, ln2g, ln2b, out, nullptr);
}

// round 4
// speedup vs baseline: 4.5547x; 1.2686x over previous
#include <cuda_runtime.h>
#include <mma.h>
#include <cstdint>

using namespace nvcuda;
typedef __half half_t;

// Problem dims: B=8, S=512, D=2048, H=32, HD=64, I=8192, NT=4096 tokens.

// ---------------- scratch (device globals; no allocation allowed) --------
__device__ float  g_tmp[4096 * 8192];    // attn_out / gate (fp32)
__device__ float  g_up [4096 * 8192];    // up / ffn_out (fp32)
__device__ float  g_h1 [4096 * 2048];    // post-LN1 (fp32)
__device__ float  g_rm [1023];           // rel_pos row means
// fp16 operands
__device__ half_t g_xh   [4096 * 2048];
__device__ half_t g_qkvh [4096 * 6144];  // fused QKV output
__device__ half_t g_ctxh [4096 * 2048];
__device__ half_t g_h1h  [4096 * 2048];
__device__ half_t g_acth [4096 * 8192];
__device__ half_t g_wqkvh[2048 * 6144];  // [K=2048][Nq|Nk|Nv]
__device__ half_t g_woh  [2048 * 2048];
__device__ half_t g_gwh  [2048 * 8192];
__device__ half_t g_uwh  [2048 * 8192];
__device__ half_t g_dwh  [8192 * 2048];

// ---------------- small helpers ------------------------------------------
__device__ __forceinline__ uint32_t smem_u32(const void* p) {
    uint32_t a;
    asm("{ .reg .u64 t; cvta.to.shared.u64 t, %1; cvt.u32.u64 %0, t; }"
        : "=r"(a) : "l"(p));
    return a;
}
__device__ __forceinline__ void cpa16(uint32_t dst, const void* src) {
    asm volatile("cp.async.cg.shared.global [%0], [%1], 16;"
                 :: "r"(dst), "l"(src) : "memory");
}
__device__ __forceinline__ void cpa_commit() {
    asm volatile("cp.async.commit_group;" ::: "memory");
}
template <int N>
__device__ __forceinline__ void cpa_wait() {
    asm volatile("cp.async.wait_group %0;" :: "n"(N) : "memory");
}

__device__ __forceinline__ float bred(float v, int op_max) {
    __shared__ float red[8];
    #pragma unroll
    for (int o = 16; o; o >>= 1) {
        float w = __shfl_xor_sync(0xffffffffu, v, o);
        v = op_max ? fmaxf(v, w) : v + w;
    }
    __syncthreads();
    if ((threadIdx.x & 31) == 0) red[threadIdx.x >> 5] = v;
    __syncthreads();
    v = red[threadIdx.x & 7];
    #pragma unroll
    for (int o = 4; o; o >>= 1) {
        float w = __shfl_xor_sync(0xffffffffu, v, o);
        v = op_max ? fmaxf(v, w) : v + w;
    }
    return v;
}

// =================== fp16 GEMM: C[M,N] = A[M,K] @ B[K,N] ==================
// Block tile 128x256, BK=32, warptile 64x64 (8 warps, 2x4), 4-stage cp.async.
#define G2_LDA  40
#define G2_LDB  264
#define G2_ASTG 10240                     // 128*40*2
#define G2_BSTG 16896                     // 32*264*2
#define G2_STG  27136
#define G2_SMEM (4 * G2_STG)              // 108544
#define G2_LDC  132

template <typename OutT>
__global__ void __launch_bounds__(256, 1) gemm2(
    const half_t* __restrict__ A, const half_t* __restrict__ B,
    OutT* __restrict__ C, int M, int N, int K)
{
    extern __shared__ __align__(128) char smem[];
    const uint32_t sb = smem_u32(smem);
    const int tid = threadIdx.x;
    const int warp = tid >> 5;
    const int bm = blockIdx.y * 128, bn = blockIdx.x * 256;
    const int wm = (warp >> 2) * 64, wn = (warp & 3) * 64;

    const int ar0 = tid >> 2,         ac0 = (tid & 3) << 3;
    const int ar1 = (tid + 256) >> 2, ac1 = ((tid + 256) & 3) << 3;
    const int brb = tid >> 5,         bc  = (tid & 31) << 3;

    const half_t* Abm = A + (size_t)bm * K;
    const half_t* Bbn = B + bn;

    auto load_stage = [&](int s, int kt) {
        const int k0 = kt * 32;
        uint32_t aB = sb + s * G2_STG;
        uint32_t bB = aB + G2_ASTG;
        cpa16(aB + (ar0 * G2_LDA + ac0) * 2, Abm + (size_t)ar0 * K + k0 + ac0);
        cpa16(aB + (ar1 * G2_LDA + ac1) * 2, Abm + (size_t)ar1 * K + k0 + ac1);
        #pragma unroll
        for (int i = 0; i < 4; i++) {
            int r = brb + 8 * i;
            cpa16(bB + (r * G2_LDB + bc) * 2, Bbn + (size_t)(k0 + r) * N + bc);
        }
    };

    wmma::fragment<wmma::accumulator, 16, 16, 16, float> acc[4][4];
    #pragma unroll
    for (int i = 0; i < 4; i++)
        #pragma unroll
        for (int j = 0; j < 4; j++)
            wmma::fill_fragment(acc[i][j], 0.0f);

    const int KT = K >> 5;
    #pragma unroll
    for (int s = 0; s < 3; s++) { load_stage(s, s); cpa_commit(); }

    for (int kt = 0; kt < KT; kt++) {
        if (kt + 3 < KT) load_stage((kt + 3) & 3, kt + 3);
        cpa_commit();
        cpa_wait<3>();
        __syncthreads();

        const int s = kt & 3;
        const half_t* As = (const half_t*)(smem + s * G2_STG);
        const half_t* Bs = (const half_t*)(smem + s * G2_STG + G2_ASTG);
        #pragma unroll
        for (int ks = 0; ks < 2; ks++) {
            wmma::fragment<wmma::matrix_a, 16, 16, 16, half_t, wmma::row_major> af[4];
            wmma::fragment<wmma::matrix_b, 16, 16, 16, half_t, wmma::row_major> bf[4];
            #pragma unroll
            for (int i = 0; i < 4; i++)
                wmma::load_matrix_sync(af[i], As + (wm + i * 16) * G2_LDA + ks * 16, G2_LDA);
            #pragma unroll
            for (int j = 0; j < 4; j++)
                wmma::load_matrix_sync(bf[j], Bs + (ks * 16) * G2_LDB + wn + j * 16, G2_LDB);
            #pragma unroll
            for (int i = 0; i < 4; i++)
                #pragma unroll
                for (int j = 0; j < 4; j++)
                    wmma::mma_sync(acc[i][j], af[i], bf[j], acc[i][j]);
        }
        __syncthreads();
    }

    // 2-phase epilogue through fp32 smem staging (128x128 per phase)
    float* Cs = (float*)smem;
    #pragma unroll
    for (int ph = 0; ph < 2; ph++) {
        __syncthreads();
        if (((warp & 3) >> 1) == ph) {
            int lwn = (warp & 3) & 1;
            #pragma unroll
            for (int i = 0; i < 4; i++)
                #pragma unroll
                for (int j = 0; j < 4; j++)
                    wmma::store_matrix_sync(Cs + (wm + i * 16) * G2_LDC + lwn * 64 + j * 16,
                                            acc[i][j], G2_LDC, wmma::mem_row_major);
        }
        __syncthreads();
        #pragma unroll
        for (int it = 0; it < 16; it++) {
            int idx = tid + 256 * it;
            int r = idx >> 5, c = (idx & 31) << 2;
            float4 v = *(float4*)(Cs + r * G2_LDC + c);
            if constexpr (sizeof(OutT) == 4) {
                *(float4*)((float*)C + (size_t)(bm + r) * N + bn + ph * 128 + c) = v;
            } else {
                half2 h0 = __floats2half2_rn(v.x, v.y);
                half2 h1 = __floats2half2_rn(v.z, v.w);
                *(uint2*)((half_t*)C + (size_t)(bm + r) * N + bn + ph * 128 + c) =
                    make_uint2(*(uint32_t*)&h0, *(uint32_t*)&h1);
            }
        }
    }
}

// =================== fused flash attention ================================
// Per block: (b, h, q-tile 128). Loop over 4 k-tiles of 128: S = QK^T/8+bias,
// online softmax, O += P@V. All in fp16 MMA, fp32 stats.
#define FL_RM   0
#define FL_QS   4096
#define FL_KS   (FL_QS + 18432)
#define FL_VS   (FL_KS + 18432)
#define FL_PS   (FL_VS + 18432)          // fp16 [128][136]
#define FL_OF   (FL_PS + 34816)          // fp32 [128][72]
#define FL_SF   (FL_OF + 36864)          // fp32 [128][132]
#define FL_M    (FL_SF + 67584)
#define FL_L    (FL_M + 512)
#define FL_CORR (FL_L + 512)
#define FL_SMEM (FL_CORR + 512)          // 200192

__global__ void __launch_bounds__(256, 1) flash_k(
    const half_t* __restrict__ qkv, const float* __restrict__ rmg,
    half_t* __restrict__ ctx)
{
    extern __shared__ __align__(128) char smem[];
    float*  rms = (float*)(smem + FL_RM);
    half_t* Qs  = (half_t*)(smem + FL_QS);   // [128][72]
    half_t* Ks  = (half_t*)(smem + FL_KS);   // [128][72]
    half_t* Vs  = (half_t*)(smem + FL_VS);   // [128][72]
    half_t* Ps  = (half_t*)(smem + FL_PS);   // [128][136]
    float*  Of  = (float*)(smem + FL_OF);    // [128][72]
    float*  Sf  = (float*)(smem + FL_SF);    // [128][132]
    float*  mS  = (float*)(smem + FL_M);
    float*  lS  = (float*)(smem + FL_L);
    float*  cS  = (float*)(smem + FL_CORR);

    const int tid = threadIdx.x, warp = tid >> 5;
    const int bz = blockIdx.y, b = bz >> 5, h = bz & 31;
    const int q0 = blockIdx.x * 128;

    for (int i = tid; i < 1023; i += 256) rms[i] = rmg[i];

    const half_t* qp = qkv + ((size_t)(b * 512 + q0)) * 6144 + h * 64;
    #pragma unroll
    for (int i = 0; i < 4; i++) {
        int idx = tid + 256 * i;
        int r = idx >> 3, c = (idx & 7) << 3;
        *(uint4*)(Qs + r * 72 + c) = *(const uint4*)(qp + (size_t)r * 6144 + c);
    }
    #pragma unroll
    for (int i = 0; i < 9; i++) {
        int idx = tid + 256 * i;
        *(float4*)(Of + idx * 4) = make_float4(0.f, 0.f, 0.f, 0.f);
    }
    if (tid < 128) { mS[tid] = -1e30f; lS[tid] = 0.0f; }
    __syncthreads();

    for (int kt = 0; kt < 4; kt++) {
        const int k0 = kt * 128;
        const half_t* kp = qkv + ((size_t)(b * 512 + k0)) * 6144 + 2048 + h * 64;
        const half_t* vp = qkv + ((size_t)(b * 512 + k0)) * 6144 + 4096 + h * 64;
        #pragma unroll
        for (int i = 0; i < 4; i++) {
            int idx = tid + 256 * i;
            int r = idx >> 3, c = (idx & 7) << 3;
            *(uint4*)(Ks + r * 72 + c) = *(const uint4*)(kp + (size_t)r * 6144 + c);
            *(uint4*)(Vs + r * 72 + c) = *(const uint4*)(vp + (size_t)r * 6144 + c);
        }
        __syncthreads();

        // ---- S = Q @ K^T : warptile 64x32 (2x4 warps over 128x128) ----
        {
            const int wm = (warp >> 2) * 64, wn = (warp & 3) * 32;
            wmma::fragment<wmma::accumulator, 16, 16, 16, float> sa[4][2];
            #pragma unroll
            for (int i = 0; i < 4; i++)
                #pragma unroll
                for (int j = 0; j < 2; j++)
                    wmma::fill_fragment(sa[i][j], 0.0f);
            #pragma unroll
            for (int ks = 0; ks < 4; ks++) {
                wmma::fragment<wmma::matrix_a, 16, 16, 16, half_t, wmma::row_major> af[4];
                wmma::fragment<wmma::matrix_b, 16, 16, 16, half_t, wmma::col_major> bf[2];
                #pragma unroll
                for (int i = 0; i < 4; i++)
                    wmma::load_matrix_sync(af[i], Qs + (wm + i * 16) * 72 + ks * 16, 72);
                #pragma unroll
                for (int j = 0; j < 2; j++)
                    wmma::load_matrix_sync(bf[j], Ks + (wn + j * 16) * 72 + ks * 16, 72);
                #pragma unroll
                for (int i = 0; i < 4; i++)
                    #pragma unroll
                    for (int j = 0; j < 2; j++)
                        wmma::mma_sync(sa[i][j], af[i], bf[j], sa[i][j]);
            }
            #pragma unroll
            for (int i = 0; i < 4; i++)
                #pragma unroll
                for (int j = 0; j < 2; j++)
                    wmma::store_matrix_sync(Sf + (wm + i * 16) * 132 + wn + j * 16,
                                            sa[i][j], 132, wmma::mem_row_major);
        }
        __syncthreads();

        // ---- online softmax: thread t -> row t>>1, half (t&1) ----
        {
            const int r = tid >> 1, hh = tid & 1, cb = hh * 64;
            float mx = -1e30f;
            #pragma unroll
            for (int c4 = 0; c4 < 16; c4++) {
                int col = cb + c4 * 4;
                float4 v = *(float4*)(Sf + r * 132 + col);
                int o = k0 + col - (q0 + r) + 511;
                v.x = v.x * 0.125f + rms[o];
                v.y = v.y * 0.125f + rms[o + 1];
                v.z = v.z * 0.125f + rms[o + 2];
                v.w = v.w * 0.125f + rms[o + 3];
                *(float4*)(Sf + r * 132 + col) = v;
                mx = fmaxf(mx, fmaxf(fmaxf(v.x, v.y), fmaxf(v.z, v.w)));
            }
            mx = fmaxf(mx, __shfl_xor_sync(0xffffffffu, mx, 1));
            float mo = mS[r];
            float mn = fmaxf(mo, mx);
            float co = __expf(mo - mn);
            float sum = 0.0f;
            #pragma unroll
            for (int c4 = 0; c4 < 16; c4++) {
                int col = cb + c4 * 4;
                float4 v = *(float4*)(Sf + r * 132 + col);
                float e0 = __expf(v.x - mn), e1 = __expf(v.y - mn);
                float e2 = __expf(v.z - mn), e3 = __expf(v.w - mn);
                sum += (e0 + e1) + (e2 + e3);
                half2 h0 = __floats2half2_rn(e0, e1);
                half2 h1 = __floats2half2_rn(e2, e3);
                *(uint2*)(Ps + r * 136 + col) =
                    make_uint2(*(uint32_t*)&h0, *(uint32_t*)&h1);
            }
            sum += __shfl_xor_sync(0xffffffffu, sum, 1);
            __syncwarp();
            if (hh == 0) {
                lS[r] = lS[r] * co + sum;
                mS[r] = mn;
                cS[r] = co;
            }
        }
        __syncthreads();

        // ---- PV: warp w -> rows 16w..16w+15, cols 0..63 ----
        {
            wmma::fragment<wmma::accumulator, 16, 16, 16, float> oa[4];
            #pragma unroll
            for (int j = 0; j < 4; j++) wmma::fill_fragment(oa[j], 0.0f);
            #pragma unroll
            for (int ks = 0; ks < 8; ks++) {
                wmma::fragment<wmma::matrix_a, 16, 16, 16, half_t, wmma::row_major> af;
                wmma::fragment<wmma::matrix_b, 16, 16, 16, half_t, wmma::row_major> bf[4];
                wmma::load_matrix_sync(af, Ps + (warp * 16) * 136 + ks * 16, 136);
                #pragma unroll
                for (int j = 0; j < 4; j++)
                    wmma::load_matrix_sync(bf[j], Vs + (ks * 16) * 72 + j * 16, 72);
                #pragma unroll
                for (int j = 0; j < 4; j++)
                    wmma::mma_sync(oa[j], af, bf[j], oa[j]);
            }
            float* St = Sf;  // reuse as [128][72] staging
            #pragma unroll
            for (int j = 0; j < 4; j++)
                wmma::store_matrix_sync(St + (warp * 16) * 72 + j * 16,
                                        oa[j], 72, wmma::mem_row_major);
        }
        __syncthreads();

        // ---- O = O*corr + stage ----
        #pragma unroll
        for (int i = 0; i < 8; i++) {
            int idx = tid + 256 * i;
            int r = idx >> 4, c = (idx & 15) << 2;
            float cr = cS[r];
            float4 ov = *(float4*)(Of + r * 72 + c);
            float4 sv = *(float4*)(Sf + r * 72 + c);
            ov.x = ov.x * cr + sv.x;
            ov.y = ov.y * cr + sv.y;
            ov.z = ov.z * cr + sv.z;
            ov.w = ov.w * cr + sv.w;
            *(float4*)(Of + r * 72 + c) = ov;
        }
        __syncthreads();
    }

    // ---- final: ctx = O / l (fp16) ----
    half_t* cp = ctx + ((size_t)(b * 512 + q0)) * 2048 + h * 64;
    #pragma unroll
    for (int i = 0; i < 8; i++) {
        int idx = tid + 256 * i;
        int r = idx >> 4, c = (idx & 15) << 2;
        float li = 1.0f / lS[r];
        float4 ov = *(float4*)(Of + r * 72 + c);
        half2 h0 = __floats2half2_rn(ov.x * li, ov.y * li);
        half2 h1 = __floats2half2_rn(ov.z * li, ov.w * li);
        *(uint2*)(cp + (size_t)r * 2048 + c) =
            make_uint2(*(uint32_t*)&h0, *(uint32_t*)&h1);
    }
}

// ---------------- residual add + layernorm (row = 2048) ------------------
__global__ void __launch_bounds__(256) add_ln_k(
    const float* __restrict__ xr, const float* __restrict__ yr,
    const float* __restrict__ g, const float* __restrict__ bt,
    float* __restrict__ out, half_t* __restrict__ hout)
{
    size_t row = blockIdx.x;
    const float4* xp = (const float4*)(xr + row * 2048);
    const float4* yp = (const float4*)(yr + row * 2048);
    int t = threadIdx.x;
    float v[8];
    #pragma unroll
    for (int i = 0; i < 2; i++) {
        float4 a = xp[t + 256 * i];
        float4 c = yp[t + 256 * i];
        v[4 * i + 0] = a.x + c.x; v[4 * i + 1] = a.y + c.y;
        v[4 * i + 2] = a.z + c.z; v[4 * i + 3] = a.w + c.w;
    }
    float s = 0.0f;
    #pragma unroll
    for (int i = 0; i < 8; i++) s += v[i];
    float mu = bred(s, 0) * (1.0f / 2048.0f);
    float qs = 0.0f;
    #pragma unroll
    for (int i = 0; i < 8; i++) { float d = v[i] - mu; qs += d * d; }
    float rstd = rsqrtf(bred(qs, 0) * (1.0f / 2048.0f) + 1e-6f);
    float4* op = (float4*)(out + row * 2048);
    #pragma unroll
    for (int i = 0; i < 2; i++) {
        int c4 = t + 256 * i;
        float4 gv = ((const float4*)g)[c4];
        float4 bv = ((const float4*)bt)[c4];
        float4 o;
        o.x = (v[4 * i + 0] - mu) * rstd * gv.x + bv.x;
        o.y = (v[4 * i + 1] - mu) * rstd * gv.y + bv.y;
        o.z = (v[4 * i + 2] - mu) * rstd * gv.z + bv.z;
        o.w = (v[4 * i + 3] - mu) * rstd * gv.w + bv.w;
        op[c4] = o;
        if (hout) {
            half2 h0 = __floats2half2_rn(o.x, o.y);
            half2 h1 = __floats2half2_rn(o.z, o.w);
            *(uint2*)(hout + row * 2048 + c4 * 4) =
                make_uint2(*(uint32_t*)&h0, *(uint32_t*)&h1);
        }
    }
}

// ---------------- silu(gate)*up -> fp16 act --------------------------------
__global__ void __launch_bounds__(256) silu_mul_k(
    const float* __restrict__ gate, const float* __restrict__ up,
    half_t* __restrict__ act)
{
    size_t i = (size_t)blockIdx.x * 256 + threadIdx.x;
    float4 gv = ((const float4*)gate)[i];
    float4 uv = ((const float4*)up)[i];
    float4 r;
    r.x = gv.x / (1.0f + __expf(-gv.x)) * uv.x;
    r.y = gv.y / (1.0f + __expf(-gv.y)) * uv.y;
    r.z = gv.z / (1.0f + __expf(-gv.z)) * uv.z;
    r.w = gv.w / (1.0f + __expf(-gv.w)) * uv.w;
    half2 h0 = __floats2half2_rn(r.x, r.y);
    half2 h1 = __floats2half2_rn(r.z, r.w);
    ((uint2*)act)[i] = make_uint2(*(uint32_t*)&h0, *(uint32_t*)&h1);
}

// ---------------- float -> half conversions --------------------------------
__global__ void __launch_bounds__(256) f2h_k(
    const float* __restrict__ in, half_t* __restrict__ out)
{
    size_t i = ((size_t)blockIdx.x * 256 + threadIdx.x) * 8;
    float4 a = *(const float4*)(in + i);
    float4 b = *(const float4*)(in + i + 4);
    half2 h0 = __floats2half2_rn(a.x, a.y);
    half2 h1 = __floats2half2_rn(a.z, a.w);
    half2 h2 = __floats2half2_rn(b.x, b.y);
    half2 h3 = __floats2half2_rn(b.z, b.w);
    *(uint4*)(out + i) = make_uint4(*(uint32_t*)&h0, *(uint32_t*)&h1,
                                    *(uint32_t*)&h2, *(uint32_t*)&h3);
}

// fp32 [2048][2048] -> fp16 slice of [2048][6144] at column offset
__global__ void __launch_bounds__(256) f2h_cat_k(
    const float* __restrict__ in, half_t* __restrict__ out)
{
    size_t i = ((size_t)blockIdx.x * 256 + threadIdx.x) * 8;
    int r = (int)(i >> 11), c = (int)(i & 2047);
    float4 a = *(const float4*)(in + i);
    float4 b = *(const float4*)(in + i + 4);
    half2 h0 = __floats2half2_rn(a.x, a.y);
    half2 h1 = __floats2half2_rn(a.z, a.w);
    half2 h2 = __floats2half2_rn(b.x, b.y);
    half2 h3 = __floats2half2_rn(b.z, b.w);
    *(uint4*)(out + (size_t)r * 6144 + c) =
        make_uint4(*(uint32_t*)&h0, *(uint32_t*)&h1,
                   *(uint32_t*)&h2, *(uint32_t*)&h3);
}

// ---------------- rel_pos row means ---------------------------------------
__global__ void rowmean_k(const float* __restrict__ rel, float* __restrict__ rm) {
    int r = blockIdx.x * 256 + threadIdx.x;
    if (r < 1023) {
        float s = 0.0f;
        #pragma unroll
        for (int d = 0; d < 64; d++) s += rel[r * 64 + d];
        rm[r] = s * (1.0f / 64.0f);
    }
}

// =================== host side ============================================
extern "C" void kernel_launch(void* const* d_in, const int* in_sizes, int n_in,
                              void* d_out, int out_size)
{
    (void)in_sizes; (void)n_in; (void)out_size;
    const float* x    = (const float*)d_in[0];
    const float* wq   = (const float*)d_in[1];
    const float* wk   = (const float*)d_in[2];
    const float* wv   = (const float*)d_in[3];
    const float* wo   = (const float*)d_in[4];
    const float* rel  = (const float*)d_in[5];
    const float* ln1g = (const float*)d_in[6];
    const float* ln1b = (const float*)d_in[7];
    const float* gw   = (const float*)d_in[8];
    const float* uw   = (const float*)d_in[9];
    const float* dw   = (const float*)d_in[10];
    const float* ln2g = (const float*)d_in[11];
    const float* ln2b = (const float*)d_in[12];
    float* out = (float*)d_out;

    float *tmp, *up, *h1, *rm;
    half_t *xh, *qkvh, *ctxh, *h1h, *acth;
    half_t *wqkvh, *woh, *gwh, *uwh, *dwh;
    cudaGetSymbolAddress((void**)&tmp,   g_tmp);
    cudaGetSymbolAddress((void**)&up,    g_up);
    cudaGetSymbolAddress((void**)&h1,    g_h1);
    cudaGetSymbolAddress((void**)&rm,    g_rm);
    cudaGetSymbolAddress((void**)&xh,    g_xh);
    cudaGetSymbolAddress((void**)&qkvh,  g_qkvh);
    cudaGetSymbolAddress((void**)&ctxh,  g_ctxh);
    cudaGetSymbolAddress((void**)&h1h,   g_h1h);
    cudaGetSymbolAddress((void**)&acth,  g_acth);
    cudaGetSymbolAddress((void**)&wqkvh, g_wqkvh);
    cudaGetSymbolAddress((void**)&woh,   g_woh);
    cudaGetSymbolAddress((void**)&gwh,   g_gwh);
    cudaGetSymbolAddress((void**)&uwh,   g_uwh);
    cudaGetSymbolAddress((void**)&dwh,   g_dwh);

    cudaFuncSetAttribute(gemm2<float>,  cudaFuncAttributeMaxDynamicSharedMemorySize, G2_SMEM);
    cudaFuncSetAttribute(gemm2<half_t>, cudaFuncAttributeMaxDynamicSharedMemorySize, G2_SMEM);
    cudaFuncSetAttribute(flash_k, cudaFuncAttributeMaxDynamicSharedMemorySize, FL_SMEM);

    // fp16 conversions
    f2h_k<<<4096, 256>>>(x, xh);
    f2h_cat_k<<<2048, 256>>>(wq, wqkvh);
    f2h_cat_k<<<2048, 256>>>(wk, wqkvh + 2048);
    f2h_cat_k<<<2048, 256>>>(wv, wqkvh + 4096);
    f2h_k<<<2048, 256>>>(wo, woh);
    f2h_k<<<8192, 256>>>(gw, gwh);
    f2h_k<<<8192, 256>>>(uw, uwh);
    f2h_k<<<8192, 256>>>(dw, dwh);
    rowmean_k<<<4, 256>>>(rel, rm);

    // fused QKV projection -> fp16 [4096, 6144]
    gemm2<half_t><<<dim3(24, 32), 256, G2_SMEM>>>(xh, wqkvh, qkvh, 4096, 6144, 2048);

    // fused flash attention -> ctxh [4096, 2048]
    flash_k<<<dim3(4, 256), 256, FL_SMEM>>>(qkvh, rm, ctxh);

    // output projection + residual + LN1
    gemm2<float><<<dim3(8, 32), 256, G2_SMEM>>>(ctxh, woh, tmp, 4096, 2048, 2048);
    add_ln_k<<<4096, 256>>>(x, tmp, ln1g, ln1b, h1, h1h);

    // FFN (SwiGLU)
    gemm2<float><<<dim3(32, 32), 256, G2_SMEM>>>(h1h, gwh, tmp, 4096, 8192, 2048);
    gemm2<float><<<dim3(32, 32), 256, G2_SMEM>>>(h1h, uwh, up,  4096, 8192, 2048);
    silu_mul_k<<<32768, 256>>>(tmp, up, acth);
    gemm2<float><<<dim3(8, 32), 256, G2_SMEM>>>(acth, dwh, up, 4096, 2048, 8192);

    // residual + LN2 -> output
    add_ln_k<<<4096, 256>>>(h1, up, ln2g, ln2b, out, nullptr);
}

// round 5
// speedup vs baseline: 4.6411x; 1.0190x over previous
#include <cuda_runtime.h>
#include <mma.h>
#include <cstdint>

using namespace nvcuda;
typedef __half half_t;

// Problem dims: B=8, S=512, D=2048, H=32, HD=64, I=8192, NT=4096 tokens.

// ---------------- scratch (device globals; no allocation allowed) --------
__device__ float  g_tmp[4096 * 8192];    // attn_out fp32 / gate fp16 (aliased)
__device__ float  g_up [4096 * 8192];    // up fp16 / ffn_out fp32 (aliased)
__device__ float  g_h1 [4096 * 2048];    // post-LN1 (fp32)
__device__ float  g_rm [1023];           // rel_pos row means
// fp16 operands
__device__ half_t g_xh   [4096 * 2048];
__device__ half_t g_qkvh [4096 * 6144];  // fused QKV output
__device__ half_t g_ctxh [4096 * 2048];
__device__ half_t g_h1h  [4096 * 2048];
__device__ half_t g_acth [4096 * 8192];
__device__ half_t g_wqkvh[2048 * 6144];  // [K=2048][Nq|Nk|Nv]
__device__ half_t g_woh  [2048 * 2048];
__device__ half_t g_gwh  [2048 * 8192];
__device__ half_t g_uwh  [2048 * 8192];
__device__ half_t g_dwh  [8192 * 2048];

// ---------------- small helpers ------------------------------------------
__device__ __forceinline__ uint32_t smem_u32(const void* p) {
    uint32_t a;
    asm("{ .reg .u64 t; cvta.to.shared.u64 t, %1; cvt.u32.u64 %0, t; }"
        : "=r"(a) : "l"(p));
    return a;
}
__device__ __forceinline__ void cpa16(uint32_t dst, const void* src) {
    asm volatile("cp.async.cg.shared.global [%0], [%1], 16;"
                 :: "r"(dst), "l"(src) : "memory");
}
__device__ __forceinline__ void cpa_commit() {
    asm volatile("cp.async.commit_group;" ::: "memory");
}
template <int N>
__device__ __forceinline__ void cpa_wait() {
    asm volatile("cp.async.wait_group %0;" :: "n"(N) : "memory");
}

__device__ __forceinline__ float bred(float v, int op_max) {
    __shared__ float red[8];
    #pragma unroll
    for (int o = 16; o; o >>= 1) {
        float w = __shfl_xor_sync(0xffffffffu, v, o);
        v = op_max ? fmaxf(v, w) : v + w;
    }
    __syncthreads();
    if ((threadIdx.x & 31) == 0) red[threadIdx.x >> 5] = v;
    __syncthreads();
    v = red[threadIdx.x & 7];
    #pragma unroll
    for (int o = 4; o; o >>= 1) {
        float w = __shfl_xor_sync(0xffffffffu, v, o);
        v = op_max ? fmaxf(v, w) : v + w;
    }
    return v;
}

// =================== fp16 GEMM: C[M,N] = A[M,K] @ B[K,N] ==================
// Block tile 128x256, BK=32, warptile 64x64 (8 warps, 2x4), 4-stage cp.async.
#define G2_LDA  40
#define G2_LDB  264
#define G2_ASTG 10240                     // 128*40*2
#define G2_BSTG 16896                     // 32*264*2
#define G2_STG  27136
#define G2_SMEM (4 * G2_STG)              // 108544
#define G2_LDC  132

template <typename OutT>
__global__ void __launch_bounds__(256, 1) gemm2(
    const half_t* __restrict__ A, const half_t* __restrict__ B,
    OutT* __restrict__ C, int M, int N, int K)
{
    extern __shared__ __align__(128) char smem[];
    const uint32_t sb = smem_u32(smem);
    const int tid = threadIdx.x;
    const int warp = tid >> 5;
    const int bm = blockIdx.y * 128, bn = blockIdx.x * 256;
    const int wm = (warp >> 2) * 64, wn = (warp & 3) * 64;

    const int ar0 = tid >> 2,         ac0 = (tid & 3) << 3;
    const int ar1 = (tid + 256) >> 2, ac1 = ((tid + 256) & 3) << 3;
    const int brb = tid >> 5,         bc  = (tid & 31) << 3;

    const half_t* Abm = A + (size_t)bm * K;
    const half_t* Bbn = B + bn;

    auto load_stage = [&](int s, int kt) {
        const int k0 = kt * 32;
        uint32_t aB = sb + s * G2_STG;
        uint32_t bB = aB + G2_ASTG;
        cpa16(aB + (ar0 * G2_LDA + ac0) * 2, Abm + (size_t)ar0 * K + k0 + ac0);
        cpa16(aB + (ar1 * G2_LDA + ac1) * 2, Abm + (size_t)ar1 * K + k0 + ac1);
        #pragma unroll
        for (int i = 0; i < 4; i++) {
            int r = brb + 8 * i;
            cpa16(bB + (r * G2_LDB + bc) * 2, Bbn + (size_t)(k0 + r) * N + bc);
        }
    };

    wmma::fragment<wmma::accumulator, 16, 16, 16, float> acc[4][4];
    #pragma unroll
    for (int i = 0; i < 4; i++)
        #pragma unroll
        for (int j = 0; j < 4; j++)
            wmma::fill_fragment(acc[i][j], 0.0f);

    const int KT = K >> 5;
    #pragma unroll
    for (int s = 0; s < 3; s++) { load_stage(s, s); cpa_commit(); }

    for (int kt = 0; kt < KT; kt++) {
        if (kt + 3 < KT) load_stage((kt + 3) & 3, kt + 3);
        cpa_commit();
        cpa_wait<3>();
        __syncthreads();

        const int s = kt & 3;
        const half_t* As = (const half_t*)(smem + s * G2_STG);
        const half_t* Bs = (const half_t*)(smem + s * G2_STG + G2_ASTG);
        #pragma unroll
        for (int ks = 0; ks < 2; ks++) {
            wmma::fragment<wmma::matrix_a, 16, 16, 16, half_t, wmma::row_major> af[4];
            wmma::fragment<wmma::matrix_b, 16, 16, 16, half_t, wmma::row_major> bf[4];
            #pragma unroll
            for (int i = 0; i < 4; i++)
                wmma::load_matrix_sync(af[i], As + (wm + i * 16) * G2_LDA + ks * 16, G2_LDA);
            #pragma unroll
            for (int j = 0; j < 4; j++)
                wmma::load_matrix_sync(bf[j], Bs + (ks * 16) * G2_LDB + wn + j * 16, G2_LDB);
            #pragma unroll
            for (int i = 0; i < 4; i++)
                #pragma unroll
                for (int j = 0; j < 4; j++)
                    wmma::mma_sync(acc[i][j], af[i], bf[j], acc[i][j]);
        }
        __syncthreads();
    }

    // 2-phase epilogue through fp32 smem staging (128x128 per phase)
    float* Cs = (float*)smem;
    #pragma unroll
    for (int ph = 0; ph < 2; ph++) {
        __syncthreads();
        if (((warp & 3) >> 1) == ph) {
            int lwn = (warp & 3) & 1;
            #pragma unroll
            for (int i = 0; i < 4; i++)
                #pragma unroll
                for (int j = 0; j < 4; j++)
                    wmma::store_matrix_sync(Cs + (wm + i * 16) * G2_LDC + lwn * 64 + j * 16,
                                            acc[i][j], G2_LDC, wmma::mem_row_major);
        }
        __syncthreads();
        #pragma unroll
        for (int it = 0; it < 16; it++) {
            int idx = tid + 256 * it;
            int r = idx >> 5, c = (idx & 31) << 2;
            float4 v = *(float4*)(Cs + r * G2_LDC + c);
            if constexpr (sizeof(OutT) == 4) {
                *(float4*)((float*)C + (size_t)(bm + r) * N + bn + ph * 128 + c) = v;
            } else {
                half2 h0 = __floats2half2_rn(v.x, v.y);
                half2 h1 = __floats2half2_rn(v.z, v.w);
                *(uint2*)((half_t*)C + (size_t)(bm + r) * N + bn + ph * 128 + c) =
                    make_uint2(*(uint32_t*)&h0, *(uint32_t*)&h1);
            }
        }
    }
}

// =================== fused flash attention ================================
#define FL_RM   0
#define FL_QS   4096
#define FL_KS   (FL_QS + 18432)
#define FL_VS   (FL_KS + 18432)
#define FL_PS   (FL_VS + 18432)          // fp16 [128][136]
#define FL_OF   (FL_PS + 34816)          // fp32 [128][72]
#define FL_SF   (FL_OF + 36864)          // fp32 [128][132]
#define FL_M    (FL_SF + 67584)
#define FL_L    (FL_M + 512)
#define FL_CORR (FL_L + 512)
#define FL_SMEM (FL_CORR + 512)          // 200192

__global__ void __launch_bounds__(256, 1) flash_k(
    const half_t* __restrict__ qkv, const float* __restrict__ rmg,
    half_t* __restrict__ ctx)
{
    extern __shared__ __align__(128) char smem[];
    float*  rms = (float*)(smem + FL_RM);
    half_t* Qs  = (half_t*)(smem + FL_QS);
    half_t* Ks  = (half_t*)(smem + FL_KS);
    half_t* Vs  = (half_t*)(smem + FL_VS);
    half_t* Ps  = (half_t*)(smem + FL_PS);
    float*  Of  = (float*)(smem + FL_OF);
    float*  Sf  = (float*)(smem + FL_SF);
    float*  mS  = (float*)(smem + FL_M);
    float*  lS  = (float*)(smem + FL_L);
    float*  cS  = (float*)(smem + FL_CORR);

    const int tid = threadIdx.x, warp = tid >> 5;
    const int bz = blockIdx.y, b = bz >> 5, h = bz & 31;
    const int q0 = blockIdx.x * 128;

    for (int i = tid; i < 1023; i += 256) rms[i] = rmg[i];

    const half_t* qp = qkv + ((size_t)(b * 512 + q0)) * 6144 + h * 64;
    #pragma unroll
    for (int i = 0; i < 4; i++) {
        int idx = tid + 256 * i;
        int r = idx >> 3, c = (idx & 7) << 3;
        *(uint4*)(Qs + r * 72 + c) = *(const uint4*)(qp + (size_t)r * 6144 + c);
    }
    #pragma unroll
    for (int i = 0; i < 9; i++) {
        int idx = tid + 256 * i;
        *(float4*)(Of + idx * 4) = make_float4(0.f, 0.f, 0.f, 0.f);
    }
    if (tid < 128) { mS[tid] = -1e30f; lS[tid] = 0.0f; }
    __syncthreads();

    for (int kt = 0; kt < 4; kt++) {
        const int k0 = kt * 128;
        const half_t* kp = qkv + ((size_t)(b * 512 + k0)) * 6144 + 2048 + h * 64;
        const half_t* vp = qkv + ((size_t)(b * 512 + k0)) * 6144 + 4096 + h * 64;
        #pragma unroll
        for (int i = 0; i < 4; i++) {
            int idx = tid + 256 * i;
            int r = idx >> 3, c = (idx & 7) << 3;
            *(uint4*)(Ks + r * 72 + c) = *(const uint4*)(kp + (size_t)r * 6144 + c);
            *(uint4*)(Vs + r * 72 + c) = *(const uint4*)(vp + (size_t)r * 6144 + c);
        }
        __syncthreads();

        // ---- S = Q @ K^T ----
        {
            const int wm = (warp >> 2) * 64, wn = (warp & 3) * 32;
            wmma::fragment<wmma::accumulator, 16, 16, 16, float> sa[4][2];
            #pragma unroll
            for (int i = 0; i < 4; i++)
                #pragma unroll
                for (int j = 0; j < 2; j++)
                    wmma::fill_fragment(sa[i][j], 0.0f);
            #pragma unroll
            for (int ks = 0; ks < 4; ks++) {
                wmma::fragment<wmma::matrix_a, 16, 16, 16, half_t, wmma::row_major> af[4];
                wmma::fragment<wmma::matrix_b, 16, 16, 16, half_t, wmma::col_major> bf[2];
                #pragma unroll
                for (int i = 0; i < 4; i++)
                    wmma::load_matrix_sync(af[i], Qs + (wm + i * 16) * 72 + ks * 16, 72);
                #pragma unroll
                for (int j = 0; j < 2; j++)
                    wmma::load_matrix_sync(bf[j], Ks + (wn + j * 16) * 72 + ks * 16, 72);
                #pragma unroll
                for (int i = 0; i < 4; i++)
                    #pragma unroll
                    for (int j = 0; j < 2; j++)
                        wmma::mma_sync(sa[i][j], af[i], bf[j], sa[i][j]);
            }
            #pragma unroll
            for (int i = 0; i < 4; i++)
                #pragma unroll
                for (int j = 0; j < 2; j++)
                    wmma::store_matrix_sync(Sf + (wm + i * 16) * 132 + wn + j * 16,
                                            sa[i][j], 132, wmma::mem_row_major);
        }
        __syncthreads();

        // ---- online softmax ----
        {
            const int r = tid >> 1, hh = tid & 1, cb = hh * 64;
            float mx = -1e30f;
            #pragma unroll
            for (int c4 = 0; c4 < 16; c4++) {
                int col = cb + c4 * 4;
                float4 v = *(float4*)(Sf + r * 132 + col);
                int o = k0 + col - (q0 + r) + 511;
                v.x = v.x * 0.125f + rms[o];
                v.y = v.y * 0.125f + rms[o + 1];
                v.z = v.z * 0.125f + rms[o + 2];
                v.w = v.w * 0.125f + rms[o + 3];
                *(float4*)(Sf + r * 132 + col) = v;
                mx = fmaxf(mx, fmaxf(fmaxf(v.x, v.y), fmaxf(v.z, v.w)));
            }
            mx = fmaxf(mx, __shfl_xor_sync(0xffffffffu, mx, 1));
            float mo = mS[r];
            float mn = fmaxf(mo, mx);
            float co = __expf(mo - mn);
            float sum = 0.0f;
            #pragma unroll
            for (int c4 = 0; c4 < 16; c4++) {
                int col = cb + c4 * 4;
                float4 v = *(float4*)(Sf + r * 132 + col);
                float e0 = __expf(v.x - mn), e1 = __expf(v.y - mn);
                float e2 = __expf(v.z - mn), e3 = __expf(v.w - mn);
                sum += (e0 + e1) + (e2 + e3);
                half2 h0 = __floats2half2_rn(e0, e1);
                half2 h1 = __floats2half2_rn(e2, e3);
                *(uint2*)(Ps + r * 136 + col) =
                    make_uint2(*(uint32_t*)&h0, *(uint32_t*)&h1);
            }
            sum += __shfl_xor_sync(0xffffffffu, sum, 1);
            __syncwarp();
            if (hh == 0) {
                lS[r] = lS[r] * co + sum;
                mS[r] = mn;
                cS[r] = co;
            }
        }
        __syncthreads();

        // ---- PV ----
        {
            wmma::fragment<wmma::accumulator, 16, 16, 16, float> oa[4];
            #pragma unroll
            for (int j = 0; j < 4; j++) wmma::fill_fragment(oa[j], 0.0f);
            #pragma unroll
            for (int ks = 0; ks < 8; ks++) {
                wmma::fragment<wmma::matrix_a, 16, 16, 16, half_t, wmma::row_major> af;
                wmma::fragment<wmma::matrix_b, 16, 16, 16, half_t, wmma::row_major> bf[4];
                wmma::load_matrix_sync(af, Ps + (warp * 16) * 136 + ks * 16, 136);
                #pragma unroll
                for (int j = 0; j < 4; j++)
                    wmma::load_matrix_sync(bf[j], Vs + (ks * 16) * 72 + j * 16, 72);
                #pragma unroll
                for (int j = 0; j < 4; j++)
                    wmma::mma_sync(oa[j], af, bf[j], oa[j]);
            }
            float* St = Sf;
            #pragma unroll
            for (int j = 0; j < 4; j++)
                wmma::store_matrix_sync(St + (warp * 16) * 72 + j * 16,
                                        oa[j], 72, wmma::mem_row_major);
        }
        __syncthreads();

        // ---- O = O*corr + stage ----
        #pragma unroll
        for (int i = 0; i < 8; i++) {
            int idx = tid + 256 * i;
            int r = idx >> 4, c = (idx & 15) << 2;
            float cr = cS[r];
            float4 ov = *(float4*)(Of + r * 72 + c);
            float4 sv = *(float4*)(Sf + r * 72 + c);
            ov.x = ov.x * cr + sv.x;
            ov.y = ov.y * cr + sv.y;
            ov.z = ov.z * cr + sv.z;
            ov.w = ov.w * cr + sv.w;
            *(float4*)(Of + r * 72 + c) = ov;
        }
        __syncthreads();
    }

    half_t* cp = ctx + ((size_t)(b * 512 + q0)) * 2048 + h * 64;
    #pragma unroll
    for (int i = 0; i < 8; i++) {
        int idx = tid + 256 * i;
        int r = idx >> 4, c = (idx & 15) << 2;
        float li = 1.0f / lS[r];
        float4 ov = *(float4*)(Of + r * 72 + c);
        half2 h0 = __floats2half2_rn(ov.x * li, ov.y * li);
        half2 h1 = __floats2half2_rn(ov.z * li, ov.w * li);
        *(uint2*)(cp + (size_t)r * 2048 + c) =
            make_uint2(*(uint32_t*)&h0, *(uint32_t*)&h1);
    }
}

// ---------------- residual add + layernorm (row = 2048) ------------------
__global__ void __launch_bounds__(256) add_ln_k(
    const float* __restrict__ xr, const float* __restrict__ yr,
    const float* __restrict__ g, const float* __restrict__ bt,
    float* __restrict__ out, half_t* __restrict__ hout)
{
    size_t row = blockIdx.x;
    const float4* xp = (const float4*)(xr + row * 2048);
    const float4* yp = (const float4*)(yr + row * 2048);
    int t = threadIdx.x;
    float v[8];
    #pragma unroll
    for (int i = 0; i < 2; i++) {
        float4 a = xp[t + 256 * i];
        float4 c = yp[t + 256 * i];
        v[4 * i + 0] = a.x + c.x; v[4 * i + 1] = a.y + c.y;
        v[4 * i + 2] = a.z + c.z; v[4 * i + 3] = a.w + c.w;
    }
    float s = 0.0f;
    #pragma unroll
    for (int i = 0; i < 8; i++) s += v[i];
    float mu = bred(s, 0) * (1.0f / 2048.0f);
    float qs = 0.0f;
    #pragma unroll
    for (int i = 0; i < 8; i++) { float d = v[i] - mu; qs += d * d; }
    float rstd = rsqrtf(bred(qs, 0) * (1.0f / 2048.0f) + 1e-6f);
    float4* op = (float4*)(out + row * 2048);
    #pragma unroll
    for (int i = 0; i < 2; i++) {
        int c4 = t + 256 * i;
        float4 gv = ((const float4*)g)[c4];
        float4 bv = ((const float4*)bt)[c4];
        float4 o;
        o.x = (v[4 * i + 0] - mu) * rstd * gv.x + bv.x;
        o.y = (v[4 * i + 1] - mu) * rstd * gv.y + bv.y;
        o.z = (v[4 * i + 2] - mu) * rstd * gv.z + bv.z;
        o.w = (v[4 * i + 3] - mu) * rstd * gv.w + bv.w;
        op[c4] = o;
        if (hout) {
            half2 h0 = __floats2half2_rn(o.x, o.y);
            half2 h1 = __floats2half2_rn(o.z, o.w);
            *(uint2*)(hout + row * 2048 + c4 * 4) =
                make_uint2(*(uint32_t*)&h0, *(uint32_t*)&h1);
        }
    }
}

// ---------------- silu(gate)*up (fp16 in) -> fp16 act ---------------------
__global__ void __launch_bounds__(256) silu_mul_h(
    const half_t* __restrict__ gate, const half_t* __restrict__ up,
    half_t* __restrict__ act)
{
    size_t i = (size_t)blockIdx.x * 256 + threadIdx.x;   // 8 halves/thread
    uint4 gp = ((const uint4*)gate)[i];
    uint4 upk = ((const uint4*)up)[i];
    const half2* g2 = (const half2*)&gp;
    const half2* u2 = (const half2*)&upk;
    uint4 r;
    half2* r2 = (half2*)&r;
    #pragma unroll
    for (int j = 0; j < 4; j++) {
        float2 gf = __half22float2(g2[j]);
        float2 uf = __half22float2(u2[j]);
        float a = gf.x / (1.0f + __expf(-gf.x)) * uf.x;
        float b = gf.y / (1.0f + __expf(-gf.y)) * uf.y;
        r2[j] = __floats2half2_rn(a, b);
    }
    ((uint4*)act)[i] = r;
}

// ---------------- fused fp32 -> fp16 conversions (single launch) ----------
__global__ void __launch_bounds__(256) f2h_multi(
    const float* __restrict__ x,  half_t* __restrict__ xo,
    const float* __restrict__ wo, half_t* __restrict__ woo,
    const float* __restrict__ gw, half_t* __restrict__ gwo,
    const float* __restrict__ uw, half_t* __restrict__ uwo,
    const float* __restrict__ dw, half_t* __restrict__ dwo)
{
    int blk = blockIdx.x;
    const float* in; half_t* out;
    if      (blk < 4096)  { in = x;  out = xo;  }
    else if (blk < 6144)  { in = wo; out = woo; blk -= 4096; }
    else if (blk < 14336) { in = gw; out = gwo; blk -= 6144; }
    else if (blk < 22528) { in = uw; out = uwo; blk -= 14336; }
    else                  { in = dw; out = dwo; blk -= 22528; }
    size_t i = ((size_t)blk * 256 + threadIdx.x) * 8;
    float4 a = *(const float4*)(in + i);
    float4 b = *(const float4*)(in + i + 4);
    half2 h0 = __floats2half2_rn(a.x, a.y);
    half2 h1 = __floats2half2_rn(a.z, a.w);
    half2 h2 = __floats2half2_rn(b.x, b.y);
    half2 h3 = __floats2half2_rn(b.z, b.w);
    *(uint4*)(out + i) = make_uint4(*(uint32_t*)&h0, *(uint32_t*)&h1,
                                    *(uint32_t*)&h2, *(uint32_t*)&h3);
}

// fp32 [2048][2048] -> fp16 slice of [2048][6144] at column offset
__global__ void __launch_bounds__(256) f2h_cat_k(
    const float* __restrict__ in, half_t* __restrict__ out)
{
    size_t i = ((size_t)blockIdx.x * 256 + threadIdx.x) * 8;
    int r = (int)(i >> 11), c = (int)(i & 2047);
    float4 a = *(const float4*)(in + i);
    float4 b = *(const float4*)(in + i + 4);
    half2 h0 = __floats2half2_rn(a.x, a.y);
    half2 h1 = __floats2half2_rn(a.z, a.w);
    half2 h2 = __floats2half2_rn(b.x, b.y);
    half2 h3 = __floats2half2_rn(b.z, b.w);
    *(uint4*)(out + (size_t)r * 6144 + c) =
        make_uint4(*(uint32_t*)&h0, *(uint32_t*)&h1,
                   *(uint32_t*)&h2, *(uint32_t*)&h3);
}

// ---------------- rel_pos row means ---------------------------------------
__global__ void rowmean_k(const float* __restrict__ rel, float* __restrict__ rm) {
    int r = blockIdx.x * 256 + threadIdx.x;
    if (r < 1023) {
        float s = 0.0f;
        #pragma unroll
        for (int d = 0; d < 64; d++) s += rel[r * 64 + d];
        rm[r] = s * (1.0f / 64.0f);
    }
}

// =================== host side ============================================
extern "C" void kernel_launch(void* const* d_in, const int* in_sizes, int n_in,
                              void* d_out, int out_size)
{
    (void)in_sizes; (void)n_in; (void)out_size;
    const float* x    = (const float*)d_in[0];
    const float* wq   = (const float*)d_in[1];
    const float* wk   = (const float*)d_in[2];
    const float* wv   = (const float*)d_in[3];
    const float* wo   = (const float*)d_in[4];
    const float* rel  = (const float*)d_in[5];
    const float* ln1g = (const float*)d_in[6];
    const float* ln1b = (const float*)d_in[7];
    const float* gw   = (const float*)d_in[8];
    const float* uw   = (const float*)d_in[9];
    const float* dw   = (const float*)d_in[10];
    const float* ln2g = (const float*)d_in[11];
    const float* ln2b = (const float*)d_in[12];
    float* out = (float*)d_out;

    float *tmp, *up, *h1, *rm;
    half_t *xh, *qkvh, *ctxh, *h1h, *acth;
    half_t *wqkvh, *woh, *gwh, *uwh, *dwh;
    cudaGetSymbolAddress((void**)&tmp,   g_tmp);
    cudaGetSymbolAddress((void**)&up,    g_up);
    cudaGetSymbolAddress((void**)&h1,    g_h1);
    cudaGetSymbolAddress((void**)&rm,    g_rm);
    cudaGetSymbolAddress((void**)&xh,    g_xh);
    cudaGetSymbolAddress((void**)&qkvh,  g_qkvh);
    cudaGetSymbolAddress((void**)&ctxh,  g_ctxh);
    cudaGetSymbolAddress((void**)&h1h,   g_h1h);
    cudaGetSymbolAddress((void**)&acth,  g_acth);
    cudaGetSymbolAddress((void**)&wqkvh, g_wqkvh);
    cudaGetSymbolAddress((void**)&woh,   g_woh);
    cudaGetSymbolAddress((void**)&gwh,   g_gwh);
    cudaGetSymbolAddress((void**)&uwh,   g_uwh);
    cudaGetSymbolAddress((void**)&dwh,   g_dwh);

    // fp16 views of the big fp32 scratch (aliased; lifetimes don't overlap)
    half_t* gate_h = (half_t*)tmp;
    half_t* up_h   = (half_t*)up;
    float*  ffn_f  = tmp;     // down-proj fp32 output (gate_h dead by then)

    cudaFuncSetAttribute(gemm2<float>,  cudaFuncAttributeMaxDynamicSharedMemorySize, G2_SMEM);
    cudaFuncSetAttribute(gemm2<half_t>, cudaFuncAttributeMaxDynamicSharedMemorySize, G2_SMEM);
    cudaFuncSetAttribute(flash_k, cudaFuncAttributeMaxDynamicSharedMemorySize, FL_SMEM);

    // launches 1-5 (so launch #6 = QKV GEMM for ncu -s 5 -c 1)
    f2h_multi<<<30720, 256>>>(x, xh, wo, woh, gw, gwh, uw, uwh, dw, dwh);
    f2h_cat_k<<<2048, 256>>>(wq, wqkvh);
    f2h_cat_k<<<2048, 256>>>(wk, wqkvh + 2048);
    f2h_cat_k<<<2048, 256>>>(wv, wqkvh + 4096);
    rowmean_k<<<4, 256>>>(rel, rm);

    // fused QKV projection -> fp16 [4096, 6144]   (launch #6)
    gemm2<half_t><<<dim3(24, 32), 256, G2_SMEM>>>(xh, wqkvh, qkvh, 4096, 6144, 2048);

    // fused flash attention -> ctxh [4096, 2048]
    flash_k<<<dim3(4, 256), 256, FL_SMEM>>>(qkvh, rm, ctxh);

    // output projection + residual + LN1 (attn_out fp32 in h1 buffer region)
    gemm2<float><<<dim3(8, 32), 256, G2_SMEM>>>(ctxh, woh, ffn_f, 4096, 2048, 2048);
    add_ln_k<<<4096, 256>>>(x, ffn_f, ln1g, ln1b, h1, h1h);

    // FFN (SwiGLU) — gate/up in fp16
    gemm2<half_t><<<dim3(32, 32), 256, G2_SMEM>>>(h1h, gwh, gate_h, 4096, 8192, 2048);
    gemm2<half_t><<<dim3(32, 32), 256, G2_SMEM>>>(h1h, uwh, up_h,  4096, 8192, 2048);
    silu_mul_h<<<16384, 256>>>(gate_h, up_h, acth);
    gemm2<float><<<dim3(8, 32), 256, G2_SMEM>>>(acth, dwh, (float*)up, 4096, 2048, 8192);

    // residual + LN2 -> output
    add_ln_k<<<4096, 256>>>(h1, (float*)up, ln2g, ln2b, out, nullptr);
}

// round 6
// speedup vs baseline: 4.6759x; 1.0075x over previous
#include <cuda_runtime.h>
#include <mma.h>
#include <cstdint>

using namespace nvcuda;
typedef __half half_t;

// Problem dims: B=8, S=512, D=2048, H=32, HD=64, I=8192, NT=4096 tokens.

// ---------------- scratch (device globals; no allocation allowed) --------
__device__ float  g_tmp[4096 * 8192];    // gate fp16 (aliased)
__device__ float  g_up [4096 * 8192];    // up fp16 / ffn_out fp32 (aliased)
__device__ float  g_h1 [4096 * 2048];    // post-LN1 (fp32)
__device__ float  g_rm [1023];           // rel_pos row means
// fp16 operands
__device__ half_t g_xh   [4096 * 2048];
__device__ half_t g_qkvh [4096 * 6144];  // fused QKV output
__device__ half_t g_ctxh [4096 * 2048];
__device__ half_t g_h1h  [4096 * 2048];
__device__ half_t g_acth [4096 * 8192];  // attn_out fp16, later silu act
__device__ half_t g_wqkvh[2048 * 6144];  // [K=2048][Nq|Nk|Nv]
__device__ half_t g_woh  [2048 * 2048];
__device__ half_t g_gwh  [2048 * 8192];
__device__ half_t g_uwh  [2048 * 8192];
__device__ half_t g_dwh  [8192 * 2048];

// ---------------- small helpers ------------------------------------------
__device__ __forceinline__ uint32_t smem_u32(const void* p) {
    uint32_t a;
    asm("{ .reg .u64 t; cvta.to.shared.u64 t, %1; cvt.u32.u64 %0, t; }"
        : "=r"(a) : "l"(p));
    return a;
}
__device__ __forceinline__ void cpa16(uint32_t dst, const void* src) {
    asm volatile("cp.async.cg.shared.global [%0], [%1], 16;"
                 :: "r"(dst), "l"(src) : "memory");
}
__device__ __forceinline__ void cpa_commit() {
    asm volatile("cp.async.commit_group;" ::: "memory");
}
template <int N>
__device__ __forceinline__ void cpa_wait() {
    asm volatile("cp.async.wait_group %0;" :: "n"(N) : "memory");
}

__device__ __forceinline__ float bred(float v, int op_max) {
    __shared__ float red[8];
    #pragma unroll
    for (int o = 16; o; o >>= 1) {
        float w = __shfl_xor_sync(0xffffffffu, v, o);
        v = op_max ? fmaxf(v, w) : v + w;
    }
    __syncthreads();
    if ((threadIdx.x & 31) == 0) red[threadIdx.x >> 5] = v;
    __syncthreads();
    v = red[threadIdx.x & 7];
    #pragma unroll
    for (int o = 4; o; o >>= 1) {
        float w = __shfl_xor_sync(0xffffffffu, v, o);
        v = op_max ? fmaxf(v, w) : v + w;
    }
    return v;
}

// =================== fp16 GEMM: C[M,N] = A[M,K] @ B[K,N] ==================
// Block tile 128x256, BK=32, warptile 64x64 (8 warps, 2x4), 4-stage cp.async.
#define G2_LDA  40
#define G2_LDB  264
#define G2_ASTG 10240
#define G2_BSTG 16896
#define G2_STG  27136
#define G2_SMEM (4 * G2_STG)              // 108544
#define G2_LDC  132

template <typename OutT>
__global__ void __launch_bounds__(256, 1) gemm2(
    const half_t* __restrict__ A, const half_t* __restrict__ B,
    OutT* __restrict__ C, int M, int N, int K)
{
    extern __shared__ __align__(128) char smem[];
    const uint32_t sb = smem_u32(smem);
    const int tid = threadIdx.x;
    const int warp = tid >> 5;
    const int bm = blockIdx.y * 128, bn = blockIdx.x * 256;
    const int wm = (warp >> 2) * 64, wn = (warp & 3) * 64;

    const int ar0 = tid >> 2,         ac0 = (tid & 3) << 3;
    const int ar1 = (tid + 256) >> 2, ac1 = ((tid + 256) & 3) << 3;
    const int brb = tid >> 5,         bc  = (tid & 31) << 3;

    const half_t* Abm = A + (size_t)bm * K;
    const half_t* Bbn = B + bn;

    auto load_stage = [&](int s, int kt) {
        const int k0 = kt * 32;
        uint32_t aB = sb + s * G2_STG;
        uint32_t bB = aB + G2_ASTG;
        cpa16(aB + (ar0 * G2_LDA + ac0) * 2, Abm + (size_t)ar0 * K + k0 + ac0);
        cpa16(aB + (ar1 * G2_LDA + ac1) * 2, Abm + (size_t)ar1 * K + k0 + ac1);
        #pragma unroll
        for (int i = 0; i < 4; i++) {
            int r = brb + 8 * i;
            cpa16(bB + (r * G2_LDB + bc) * 2, Bbn + (size_t)(k0 + r) * N + bc);
        }
    };

    wmma::fragment<wmma::accumulator, 16, 16, 16, float> acc[4][4];
    #pragma unroll
    for (int i = 0; i < 4; i++)
        #pragma unroll
        for (int j = 0; j < 4; j++)
            wmma::fill_fragment(acc[i][j], 0.0f);

    const int KT = K >> 5;
    #pragma unroll
    for (int s = 0; s < 3; s++) { load_stage(s, s); cpa_commit(); }

    for (int kt = 0; kt < KT; kt++) {
        if (kt + 3 < KT) load_stage((kt + 3) & 3, kt + 3);
        cpa_commit();
        cpa_wait<3>();
        __syncthreads();

        const int s = kt & 3;
        const half_t* As = (const half_t*)(smem + s * G2_STG);
        const half_t* Bs = (const half_t*)(smem + s * G2_STG + G2_ASTG);
        #pragma unroll
        for (int ks = 0; ks < 2; ks++) {
            wmma::fragment<wmma::matrix_a, 16, 16, 16, half_t, wmma::row_major> af[4];
            wmma::fragment<wmma::matrix_b, 16, 16, 16, half_t, wmma::row_major> bf[4];
            #pragma unroll
            for (int i = 0; i < 4; i++)
                wmma::load_matrix_sync(af[i], As + (wm + i * 16) * G2_LDA + ks * 16, G2_LDA);
            #pragma unroll
            for (int j = 0; j < 4; j++)
                wmma::load_matrix_sync(bf[j], Bs + (ks * 16) * G2_LDB + wn + j * 16, G2_LDB);
            #pragma unroll
            for (int i = 0; i < 4; i++)
                #pragma unroll
                for (int j = 0; j < 4; j++)
                    wmma::mma_sync(acc[i][j], af[i], bf[j], acc[i][j]);
        }
        __syncthreads();
    }

    // 2-phase epilogue through fp32 smem staging (128x128 per phase)
    float* Cs = (float*)smem;
    #pragma unroll
    for (int ph = 0; ph < 2; ph++) {
        __syncthreads();
        if (((warp & 3) >> 1) == ph) {
            int lwn = (warp & 3) & 1;
            #pragma unroll
            for (int i = 0; i < 4; i++)
                #pragma unroll
                for (int j = 0; j < 4; j++)
                    wmma::store_matrix_sync(Cs + (wm + i * 16) * G2_LDC + lwn * 64 + j * 16,
                                            acc[i][j], G2_LDC, wmma::mem_row_major);
        }
        __syncthreads();
        #pragma unroll
        for (int it = 0; it < 16; it++) {
            int idx = tid + 256 * it;
            int r = idx >> 5, c = (idx & 31) << 2;
            float4 v = *(float4*)(Cs + r * G2_LDC + c);
            if constexpr (sizeof(OutT) == 4) {
                *(float4*)((float*)C + (size_t)(bm + r) * N + bn + ph * 128 + c) = v;
            } else {
                half2 h0 = __floats2half2_rn(v.x, v.y);
                half2 h1 = __floats2half2_rn(v.z, v.w);
                *(uint2*)((half_t*)C + (size_t)(bm + r) * N + bn + ph * 128 + c) =
                    make_uint2(*(uint32_t*)&h0, *(uint32_t*)&h1);
            }
        }
    }
}

// =================== fused flash attention ================================
#define FL_RM   0
#define FL_QS   4096
#define FL_KS   (FL_QS + 18432)
#define FL_VS   (FL_KS + 18432)
#define FL_PS   (FL_VS + 18432)          // fp16 [128][136]
#define FL_OF   (FL_PS + 34816)          // fp32 [128][72]
#define FL_SF   (FL_OF + 36864)          // fp32 [128][132]
#define FL_M    (FL_SF + 67584)
#define FL_L    (FL_M + 512)
#define FL_CORR (FL_L + 512)
#define FL_SMEM (FL_CORR + 512)          // 200192

__global__ void __launch_bounds__(256, 1) flash_k(
    const half_t* __restrict__ qkv, const float* __restrict__ rmg,
    half_t* __restrict__ ctx)
{
    extern __shared__ __align__(128) char smem[];
    float*  rms = (float*)(smem + FL_RM);
    half_t* Qs  = (half_t*)(smem + FL_QS);
    half_t* Ks  = (half_t*)(smem + FL_KS);
    half_t* Vs  = (half_t*)(smem + FL_VS);
    half_t* Ps  = (half_t*)(smem + FL_PS);
    float*  Of  = (float*)(smem + FL_OF);
    float*  Sf  = (float*)(smem + FL_SF);
    float*  mS  = (float*)(smem + FL_M);
    float*  lS  = (float*)(smem + FL_L);
    float*  cS  = (float*)(smem + FL_CORR);

    const int tid = threadIdx.x, warp = tid >> 5;
    const int bz = blockIdx.y, b = bz >> 5, h = bz & 31;
    const int q0 = blockIdx.x * 128;

    for (int i = tid; i < 1023; i += 256) rms[i] = rmg[i];

    const half_t* qp = qkv + ((size_t)(b * 512 + q0)) * 6144 + h * 64;
    #pragma unroll
    for (int i = 0; i < 4; i++) {
        int idx = tid + 256 * i;
        int r = idx >> 3, c = (idx & 7) << 3;
        *(uint4*)(Qs + r * 72 + c) = *(const uint4*)(qp + (size_t)r * 6144 + c);
    }
    #pragma unroll
    for (int i = 0; i < 9; i++) {
        int idx = tid + 256 * i;
        *(float4*)(Of + idx * 4) = make_float4(0.f, 0.f, 0.f, 0.f);
    }
    if (tid < 128) { mS[tid] = -1e30f; lS[tid] = 0.0f; }
    __syncthreads();

    for (int kt = 0; kt < 4; kt++) {
        const int k0 = kt * 128;
        const half_t* kp = qkv + ((size_t)(b * 512 + k0)) * 6144 + 2048 + h * 64;
        const half_t* vp = qkv + ((size_t)(b * 512 + k0)) * 6144 + 4096 + h * 64;
        #pragma unroll
        for (int i = 0; i < 4; i++) {
            int idx = tid + 256 * i;
            int r = idx >> 3, c = (idx & 7) << 3;
            *(uint4*)(Ks + r * 72 + c) = *(const uint4*)(kp + (size_t)r * 6144 + c);
            *(uint4*)(Vs + r * 72 + c) = *(const uint4*)(vp + (size_t)r * 6144 + c);
        }
        __syncthreads();

        // ---- S = Q @ K^T ----
        {
            const int wm = (warp >> 2) * 64, wn = (warp & 3) * 32;
            wmma::fragment<wmma::accumulator, 16, 16, 16, float> sa[4][2];
            #pragma unroll
            for (int i = 0; i < 4; i++)
                #pragma unroll
                for (int j = 0; j < 2; j++)
                    wmma::fill_fragment(sa[i][j], 0.0f);
            #pragma unroll
            for (int ks = 0; ks < 4; ks++) {
                wmma::fragment<wmma::matrix_a, 16, 16, 16, half_t, wmma::row_major> af[4];
                wmma::fragment<wmma::matrix_b, 16, 16, 16, half_t, wmma::col_major> bf[2];
                #pragma unroll
                for (int i = 0; i < 4; i++)
                    wmma::load_matrix_sync(af[i], Qs + (wm + i * 16) * 72 + ks * 16, 72);
                #pragma unroll
                for (int j = 0; j < 2; j++)
                    wmma::load_matrix_sync(bf[j], Ks + (wn + j * 16) * 72 + ks * 16, 72);
                #pragma unroll
                for (int i = 0; i < 4; i++)
                    #pragma unroll
                    for (int j = 0; j < 2; j++)
                        wmma::mma_sync(sa[i][j], af[i], bf[j], sa[i][j]);
            }
            #pragma unroll
            for (int i = 0; i < 4; i++)
                #pragma unroll
                for (int j = 0; j < 2; j++)
                    wmma::store_matrix_sync(Sf + (wm + i * 16) * 132 + wn + j * 16,
                                            sa[i][j], 132, wmma::mem_row_major);
        }
        __syncthreads();

        // ---- online softmax ----
        {
            const int r = tid >> 1, hh = tid & 1, cb = hh * 64;
            float mx = -1e30f;
            #pragma unroll
            for (int c4 = 0; c4 < 16; c4++) {
                int col = cb + c4 * 4;
                float4 v = *(float4*)(Sf + r * 132 + col);
                int o = k0 + col - (q0 + r) + 511;
                v.x = v.x * 0.125f + rms[o];
                v.y = v.y * 0.125f + rms[o + 1];
                v.z = v.z * 0.125f + rms[o + 2];
                v.w = v.w * 0.125f + rms[o + 3];
                *(float4*)(Sf + r * 132 + col) = v;
                mx = fmaxf(mx, fmaxf(fmaxf(v.x, v.y), fmaxf(v.z, v.w)));
            }
            mx = fmaxf(mx, __shfl_xor_sync(0xffffffffu, mx, 1));
            float mo = mS[r];
            float mn = fmaxf(mo, mx);
            float co = __expf(mo - mn);
            float sum = 0.0f;
            #pragma unroll
            for (int c4 = 0; c4 < 16; c4++) {
                int col = cb + c4 * 4;
                float4 v = *(float4*)(Sf + r * 132 + col);
                float e0 = __expf(v.x - mn), e1 = __expf(v.y - mn);
                float e2 = __expf(v.z - mn), e3 = __expf(v.w - mn);
                sum += (e0 + e1) + (e2 + e3);
                half2 h0 = __floats2half2_rn(e0, e1);
                half2 h1 = __floats2half2_rn(e2, e3);
                *(uint2*)(Ps + r * 136 + col) =
                    make_uint2(*(uint32_t*)&h0, *(uint32_t*)&h1);
            }
            sum += __shfl_xor_sync(0xffffffffu, sum, 1);
            __syncwarp();
            if (hh == 0) {
                lS[r] = lS[r] * co + sum;
                mS[r] = mn;
                cS[r] = co;
            }
        }
        __syncthreads();

        // ---- PV ----
        {
            wmma::fragment<wmma::accumulator, 16, 16, 16, float> oa[4];
            #pragma unroll
            for (int j = 0; j < 4; j++) wmma::fill_fragment(oa[j], 0.0f);
            #pragma unroll
            for (int ks = 0; ks < 8; ks++) {
                wmma::fragment<wmma::matrix_a, 16, 16, 16, half_t, wmma::row_major> af;
                wmma::fragment<wmma::matrix_b, 16, 16, 16, half_t, wmma::row_major> bf[4];
                wmma::load_matrix_sync(af, Ps + (warp * 16) * 136 + ks * 16, 136);
                #pragma unroll
                for (int j = 0; j < 4; j++)
                    wmma::load_matrix_sync(bf[j], Vs + (ks * 16) * 72 + j * 16, 72);
                #pragma unroll
                for (int j = 0; j < 4; j++)
                    wmma::mma_sync(oa[j], af, bf[j], oa[j]);
            }
            float* St = Sf;
            #pragma unroll
            for (int j = 0; j < 4; j++)
                wmma::store_matrix_sync(St + (warp * 16) * 72 + j * 16,
                                        oa[j], 72, wmma::mem_row_major);
        }
        __syncthreads();

        // ---- O = O*corr + stage ----
        #pragma unroll
        for (int i = 0; i < 8; i++) {
            int idx = tid + 256 * i;
            int r = idx >> 4, c = (idx & 15) << 2;
            float cr = cS[r];
            float4 ov = *(float4*)(Of + r * 72 + c);
            float4 sv = *(float4*)(Sf + r * 72 + c);
            ov.x = ov.x * cr + sv.x;
            ov.y = ov.y * cr + sv.y;
            ov.z = ov.z * cr + sv.z;
            ov.w = ov.w * cr + sv.w;
            *(float4*)(Of + r * 72 + c) = ov;
        }
        __syncthreads();
    }

    half_t* cp = ctx + ((size_t)(b * 512 + q0)) * 2048 + h * 64;
    #pragma unroll
    for (int i = 0; i < 8; i++) {
        int idx = tid + 256 * i;
        int r = idx >> 4, c = (idx & 15) << 2;
        float li = 1.0f / lS[r];
        float4 ov = *(float4*)(Of + r * 72 + c);
        half2 h0 = __floats2half2_rn(ov.x * li, ov.y * li);
        half2 h1 = __floats2half2_rn(ov.z * li, ov.w * li);
        *(uint2*)(cp + (size_t)r * 2048 + c) =
            make_uint2(*(uint32_t*)&h0, *(uint32_t*)&h1);
    }
}

// ---------------- residual add + layernorm (row = 2048) ------------------
// YT = float or half (the non-residual summand)
template <typename YT>
__global__ void __launch_bounds__(256) add_ln_k(
    const float* __restrict__ xr, const YT* __restrict__ yr,
    const float* __restrict__ g, const float* __restrict__ bt,
    float* __restrict__ out, half_t* __restrict__ hout)
{
    size_t row = blockIdx.x;
    const float4* xp = (const float4*)(xr + row * 2048);
    int t = threadIdx.x;
    float v[8];
    #pragma unroll
    for (int i = 0; i < 2; i++) {
        int c4 = t + 256 * i;
        float4 a = xp[c4];
        float yv[4];
        if constexpr (sizeof(YT) == 4) {
            float4 c = *(const float4*)((const float*)yr + row * 2048 + c4 * 4);
            yv[0] = c.x; yv[1] = c.y; yv[2] = c.z; yv[3] = c.w;
        } else {
            uint2 p = *(const uint2*)((const half_t*)yr + row * 2048 + c4 * 4);
            float2 f0 = __half22float2(*(half2*)&p.x);
            float2 f1 = __half22float2(*(half2*)&p.y);
            yv[0] = f0.x; yv[1] = f0.y; yv[2] = f1.x; yv[3] = f1.y;
        }
        v[4 * i + 0] = a.x + yv[0]; v[4 * i + 1] = a.y + yv[1];
        v[4 * i + 2] = a.z + yv[2]; v[4 * i + 3] = a.w + yv[3];
    }
    float s = 0.0f;
    #pragma unroll
    for (int i = 0; i < 8; i++) s += v[i];
    float mu = bred(s, 0) * (1.0f / 2048.0f);
    float qs = 0.0f;
    #pragma unroll
    for (int i = 0; i < 8; i++) { float d = v[i] - mu; qs += d * d; }
    float rstd = rsqrtf(bred(qs, 0) * (1.0f / 2048.0f) + 1e-6f);
    float4* op = (float4*)(out + row * 2048);
    #pragma unroll
    for (int i = 0; i < 2; i++) {
        int c4 = t + 256 * i;
        float4 gv = ((const float4*)g)[c4];
        float4 bv = ((const float4*)bt)[c4];
        float4 o;
        o.x = (v[4 * i + 0] - mu) * rstd * gv.x + bv.x;
        o.y = (v[4 * i + 1] - mu) * rstd * gv.y + bv.y;
        o.z = (v[4 * i + 2] - mu) * rstd * gv.z + bv.z;
        o.w = (v[4 * i + 3] - mu) * rstd * gv.w + bv.w;
        op[c4] = o;
        if (hout) {
            half2 h0 = __floats2half2_rn(o.x, o.y);
            half2 h1 = __floats2half2_rn(o.z, o.w);
            *(uint2*)(hout + row * 2048 + c4 * 4) =
                make_uint2(*(uint32_t*)&h0, *(uint32_t*)&h1);
        }
    }
}

// ---------------- silu(gate)*up (fp16 in) -> fp16 act ---------------------
__global__ void __launch_bounds__(256) silu_mul_h(
    const half_t* __restrict__ gate, const half_t* __restrict__ up,
    half_t* __restrict__ act)
{
    size_t i = (size_t)blockIdx.x * 256 + threadIdx.x;   // 8 halves/thread
    uint4 gp = ((const uint4*)gate)[i];
    uint4 upk = ((const uint4*)up)[i];
    const half2* g2 = (const half2*)&gp;
    const half2* u2 = (const half2*)&upk;
    uint4 r;
    half2* r2 = (half2*)&r;
    #pragma unroll
    for (int j = 0; j < 4; j++) {
        float2 gf = __half22float2(g2[j]);
        float2 uf = __half22float2(u2[j]);
        float a = gf.x / (1.0f + __expf(-gf.x)) * uf.x;
        float b = gf.y / (1.0f + __expf(-gf.y)) * uf.y;
        r2[j] = __floats2half2_rn(a, b);
    }
    ((uint4*)act)[i] = r;
}

// ---------------- mega conversion: ALL fp32->fp16 + rel rowmean -----------
// Each block converts a 4096-float contiguous chunk (16 floats/thread,
// 4x16B loads in flight). Blocks 18432..18435 compute rel_pos row means.
__device__ __forceinline__ void conv16(const float* in, half_t* out) {
    float4 a0 = *(const float4*)(in + 0);
    float4 a1 = *(const float4*)(in + 4);
    float4 a2 = *(const float4*)(in + 8);
    float4 a3 = *(const float4*)(in + 12);
    half2 h0 = __floats2half2_rn(a0.x, a0.y), h1 = __floats2half2_rn(a0.z, a0.w);
    half2 h2 = __floats2half2_rn(a1.x, a1.y), h3 = __floats2half2_rn(a1.z, a1.w);
    half2 h4 = __floats2half2_rn(a2.x, a2.y), h5 = __floats2half2_rn(a2.z, a2.w);
    half2 h6 = __floats2half2_rn(a3.x, a3.y), h7 = __floats2half2_rn(a3.z, a3.w);
    *(uint4*)(out + 0) = make_uint4(*(uint32_t*)&h0, *(uint32_t*)&h1,
                                    *(uint32_t*)&h2, *(uint32_t*)&h3);
    *(uint4*)(out + 8) = make_uint4(*(uint32_t*)&h4, *(uint32_t*)&h5,
                                    *(uint32_t*)&h6, *(uint32_t*)&h7);
}

__global__ void __launch_bounds__(256) conv_all(
    const float* __restrict__ x,  half_t* __restrict__ xo,
    const float* __restrict__ wq, const float* __restrict__ wk,
    const float* __restrict__ wv, half_t* __restrict__ wqkv,
    const float* __restrict__ wo, half_t* __restrict__ woo,
    const float* __restrict__ gw, half_t* __restrict__ gwo,
    const float* __restrict__ uw, half_t* __restrict__ uwo,
    const float* __restrict__ dw, half_t* __restrict__ dwo,
    const float* __restrict__ rel, float* __restrict__ rm)
{
    int blk = blockIdx.x;
    const int t = threadIdx.x;

    if (blk >= 18432) {                     // rowmean: 4 blocks
        int r = (blk - 18432) * 256 + t;
        if (r < 1023) {
            float s = 0.0f;
            #pragma unroll
            for (int d = 0; d < 64; d += 4) {
                float4 vv = *(const float4*)(rel + (size_t)r * 64 + d);
                s += (vv.x + vv.y) + (vv.z + vv.w);
            }
            rm[r] = s * (1.0f / 64.0f);
        }
        return;
    }

    if (blk < 2048) {                        // x -> xh
        size_t i = ((size_t)blk * 256 + t) * 16;
        conv16(x + i, xo + i);
        return;
    }
    if (blk < 5120) {                        // wq/wk/wv -> wqkv (cat)
        int sec = (blk - 2048) >> 10;        // 0,1,2
        const float* in = sec == 0 ? wq : (sec == 1 ? wk : wv);
        size_t i = ((size_t)((blk - 2048) & 1023) * 256 + t) * 16;
        int r = (int)(i >> 11), c = (int)(i & 2047);
        conv16(in + i, wqkv + (size_t)r * 6144 + sec * 2048 + c);
        return;
    }
    if (blk < 6144) {                        // wo
        size_t i = ((size_t)(blk - 5120) * 256 + t) * 16;
        conv16(wo + i, woo + i);
        return;
    }
    if (blk < 10240) {                       // gw
        size_t i = ((size_t)(blk - 6144) * 256 + t) * 16;
        conv16(gw + i, gwo + i);
        return;
    }
    if (blk < 14336) {                       // uw
        size_t i = ((size_t)(blk - 10240) * 256 + t) * 16;
        conv16(uw + i, uwo + i);
        return;
    }
    // dw
    size_t i = ((size_t)(blk - 14336) * 256 + t) * 16;
    conv16(dw + i, dwo + i);
}

// =================== host side ============================================
extern "C" void kernel_launch(void* const* d_in, const int* in_sizes, int n_in,
                              void* d_out, int out_size)
{
    (void)in_sizes; (void)n_in; (void)out_size;
    const float* x    = (const float*)d_in[0];
    const float* wq   = (const float*)d_in[1];
    const float* wk   = (const float*)d_in[2];
    const float* wv   = (const float*)d_in[3];
    const float* wo   = (const float*)d_in[4];
    const float* rel  = (const float*)d_in[5];
    const float* ln1g = (const float*)d_in[6];
    const float* ln1b = (const float*)d_in[7];
    const float* gw   = (const float*)d_in[8];
    const float* uw   = (const float*)d_in[9];
    const float* dw   = (const float*)d_in[10];
    const float* ln2g = (const float*)d_in[11];
    const float* ln2b = (const float*)d_in[12];
    float* out = (float*)d_out;

    float *tmp, *up, *h1, *rm;
    half_t *xh, *qkvh, *ctxh, *h1h, *acth;
    half_t *wqkvh, *woh, *gwh, *uwh, *dwh;
    cudaGetSymbolAddress((void**)&tmp,   g_tmp);
    cudaGetSymbolAddress((void**)&up,    g_up);
    cudaGetSymbolAddress((void**)&h1,    g_h1);
    cudaGetSymbolAddress((void**)&rm,    g_rm);
    cudaGetSymbolAddress((void**)&xh,    g_xh);
    cudaGetSymbolAddress((void**)&qkvh,  g_qkvh);
    cudaGetSymbolAddress((void**)&ctxh,  g_ctxh);
    cudaGetSymbolAddress((void**)&h1h,   g_h1h);
    cudaGetSymbolAddress((void**)&acth,  g_acth);
    cudaGetSymbolAddress((void**)&wqkvh, g_wqkvh);
    cudaGetSymbolAddress((void**)&woh,   g_woh);
    cudaGetSymbolAddress((void**)&gwh,   g_gwh);
    cudaGetSymbolAddress((void**)&uwh,   g_uwh);
    cudaGetSymbolAddress((void**)&dwh,   g_dwh);

    // aliases (lifetimes don't overlap)
    half_t* gate_h = (half_t*)tmp;
    half_t* up_h   = (half_t*)up;
    half_t* attn_h = acth;          // attn_out fp16 (dead before silu writes)
    float*  ffn_f  = (float*)up;    // down-proj fp32 out (up_h dead by then)

    cudaFuncSetAttribute(gemm2<float>,  cudaFuncAttributeMaxDynamicSharedMemorySize, G2_SMEM);
    cudaFuncSetAttribute(gemm2<half_t>, cudaFuncAttributeMaxDynamicSharedMemorySize, G2_SMEM);
    cudaFuncSetAttribute(flash_k, cudaFuncAttributeMaxDynamicSharedMemorySize, FL_SMEM);

    // #1: all conversions + rowmean in one launch
    conv_all<<<18436, 256>>>(x, xh, wq, wk, wv, wqkvh, wo, woh,
                             gw, gwh, uw, uwh, dw, dwh, rel, rm);

    // #2: fused QKV projection (profiled launch)
    gemm2<half_t><<<dim3(24, 32), 256, G2_SMEM>>>(xh, wqkvh, qkvh, 4096, 6144, 2048);

    // #3: fused flash attention
    flash_k<<<dim3(4, 256), 256, FL_SMEM>>>(qkvh, rm, ctxh);

    // #4-5: output projection (fp16 out) + residual + LN1
    gemm2<half_t><<<dim3(8, 32), 256, G2_SMEM>>>(ctxh, woh, attn_h, 4096, 2048, 2048);
    add_ln_k<half_t><<<4096, 256>>>(x, attn_h, ln1g, ln1b, h1, h1h);

    // #6-9: FFN (SwiGLU), gate/up fp16
    gemm2<half_t><<<dim3(32, 32), 256, G2_SMEM>>>(h1h, gwh, gate_h, 4096, 8192, 2048);
    gemm2<half_t><<<dim3(32, 32), 256, G2_SMEM>>>(h1h, uwh, up_h,  4096, 8192, 2048);
    silu_mul_h<<<16384, 256>>>(gate_h, up_h, acth);
    gemm2<float><<<dim3(8, 32), 256, G2_SMEM>>>(acth, dwh, ffn_f, 4096, 2048, 8192);

    // #10: residual + LN2 -> output
    add_ln_k<float><<<4096, 256>>>(h1, ffn_f, ln2g, ln2b, out, nullptr);
}

// round 7
// speedup vs baseline: 4.7729x; 1.0207x over previous
#include <cuda_runtime.h>
#include <mma.h>
#include <cstdint>

using namespace nvcuda;
typedef __half half_t;

// Problem dims: B=8, S=512, D=2048, H=32, HD=64, I=8192, NT=4096 tokens.

// ---------------- scratch (device globals; no allocation allowed) --------
__device__ float  g_tmp[4096 * 8192];    // gate fp16 (aliased)
__device__ float  g_up [4096 * 8192];    // up fp16 / ffn_out fp32 (aliased)
__device__ float  g_h1 [4096 * 2048];    // post-LN1 (fp32)
__device__ float  g_rm [1023];           // rel_pos row means
// fp16 operands
__device__ half_t g_xh   [4096 * 2048];
__device__ half_t g_qkvh [4096 * 6144];  // fused QKV output
__device__ half_t g_ctxh [4096 * 2048];
__device__ half_t g_h1h  [4096 * 2048];
__device__ half_t g_acth [4096 * 8192];  // attn_out fp16, later silu act
__device__ half_t g_wqkvh[2048 * 6144];  // [K=2048][Nq|Nk|Nv]
__device__ half_t g_woh  [2048 * 2048];
__device__ half_t g_gwh  [2048 * 8192];
__device__ half_t g_uwh  [2048 * 8192];
__device__ half_t g_dwh  [8192 * 2048];

// ---------------- small helpers ------------------------------------------
__device__ __forceinline__ uint32_t smem_u32(const void* p) {
    uint32_t a;
    asm("{ .reg .u64 t; cvta.to.shared.u64 t, %1; cvt.u32.u64 %0, t; }"
        : "=r"(a) : "l"(p));
    return a;
}
__device__ __forceinline__ void cpa16(uint32_t dst, const void* src) {
    asm volatile("cp.async.cg.shared.global [%0], [%1], 16;"
                 :: "r"(dst), "l"(src) : "memory");
}
__device__ __forceinline__ void cpa_commit() {
    asm volatile("cp.async.commit_group;" ::: "memory");
}
template <int N>
__device__ __forceinline__ void cpa_wait() {
    asm volatile("cp.async.wait_group %0;" :: "n"(N) : "memory");
}

__device__ __forceinline__ float bred(float v, int op_max) {
    __shared__ float red[8];
    #pragma unroll
    for (int o = 16; o; o >>= 1) {
        float w = __shfl_xor_sync(0xffffffffu, v, o);
        v = op_max ? fmaxf(v, w) : v + w;
    }
    __syncthreads();
    if ((threadIdx.x & 31) == 0) red[threadIdx.x >> 5] = v;
    __syncthreads();
    v = red[threadIdx.x & 7];
    #pragma unroll
    for (int o = 4; o; o >>= 1) {
        float w = __shfl_xor_sync(0xffffffffu, v, o);
        v = op_max ? fmaxf(v, w) : v + w;
    }
    return v;
}

// =================== fp16 GEMM: C[M,N] = A[M,K] @ B[K,N] ==================
// Block tile 128xBN (BN=128 or 256), BK=32, 8 warps (2x4), warptile 64x(BN/4),
// 4-stage cp.async pipeline with ONE __syncthreads per K-iteration.
#define G2_LDA   40
#define G2_ASTG  10240                    // 128*40*2
#define G2_LDC   132

template <int BN> struct G2C {
    static constexpr int LDB  = BN + 8;
    static constexpr int BSTG = 32 * LDB * 2;
    static constexpr int STG  = G2_ASTG + BSTG;
    static constexpr int SMEM = 4 * STG;
    static constexpr int NJ   = BN / 64;   // 16-wide B frags per warp
};

template <int BN, typename OutT>
__global__ void __launch_bounds__(256, 1) gemm2(
    const half_t* __restrict__ A, const half_t* __restrict__ B,
    OutT* __restrict__ C, int M, int N, int K)
{
    using CF = G2C<BN>;
    extern __shared__ __align__(128) char smem[];
    const uint32_t sb = smem_u32(smem);
    const int tid = threadIdx.x;
    const int warp = tid >> 5;
    const int bm = blockIdx.y * 128, bn = blockIdx.x * BN;
    const int wm = (warp >> 2) * 64, wn = (warp & 3) * (BN / 4);

    // A copy coords: 2 chunks of 16B per thread (128x32 fp16)
    const int ar0 = tid >> 2,         ac0 = (tid & 3) << 3;
    const int ar1 = (tid + 256) >> 2, ac1 = ((tid + 256) & 3) << 3;
    // B copy coords: NJ chunks per thread (32xBN fp16), cpr = BN/8 chunks/row
    constexpr int CPR = BN / 8;

    const half_t* Abm = A + (size_t)bm * K;
    const half_t* Bbn = B + bn;

    auto load_stage = [&](int s, int kt) {
        const int k0 = kt * 32;
        uint32_t aB = sb + s * CF::STG;
        uint32_t bB = aB + G2_ASTG;
        cpa16(aB + (ar0 * G2_LDA + ac0) * 2, Abm + (size_t)ar0 * K + k0 + ac0);
        cpa16(aB + (ar1 * G2_LDA + ac1) * 2, Abm + (size_t)ar1 * K + k0 + ac1);
        #pragma unroll
        for (int i = 0; i < CF::NJ; i++) {
            int ci = tid + 256 * i;
            int r = ci / CPR, c = (ci % CPR) << 3;
            cpa16(bB + (r * CF::LDB + c) * 2, Bbn + (size_t)(k0 + r) * N + c);
        }
    };

    wmma::fragment<wmma::accumulator, 16, 16, 16, float> acc[4][CF::NJ];
    #pragma unroll
    for (int i = 0; i < 4; i++)
        #pragma unroll
        for (int j = 0; j < CF::NJ; j++)
            wmma::fill_fragment(acc[i][j], 0.0f);

    const int KT = K >> 5;
    #pragma unroll
    for (int s = 0; s < 3; s++) { load_stage(s, s); cpa_commit(); }

    for (int kt = 0; kt < KT; kt++) {
        cpa_wait<2>();           // stage kt resident
        __syncthreads();         // also: all warps done reading stage (kt-1)&3

        // issue next load into stage (kt+3)&3 == (kt-1)&3 — safe after sync
        if (kt + 3 < KT) load_stage((kt + 3) & 3, kt + 3);
        cpa_commit();            // one group per iteration (may be empty)

        const int s = kt & 3;
        const half_t* As = (const half_t*)(smem + s * CF::STG);
        const half_t* Bs = (const half_t*)(smem + s * CF::STG + G2_ASTG);
        #pragma unroll
        for (int ks = 0; ks < 2; ks++) {
            wmma::fragment<wmma::matrix_a, 16, 16, 16, half_t, wmma::row_major> af[4];
            wmma::fragment<wmma::matrix_b, 16, 16, 16, half_t, wmma::row_major> bf[CF::NJ];
            #pragma unroll
            for (int i = 0; i < 4; i++)
                wmma::load_matrix_sync(af[i], As + (wm + i * 16) * G2_LDA + ks * 16, G2_LDA);
            #pragma unroll
            for (int j = 0; j < CF::NJ; j++)
                wmma::load_matrix_sync(bf[j], Bs + (ks * 16) * CF::LDB + wn + j * 16, CF::LDB);
            #pragma unroll
            for (int i = 0; i < 4; i++)
                #pragma unroll
                for (int j = 0; j < CF::NJ; j++)
                    wmma::mma_sync(acc[i][j], af[i], bf[j], acc[i][j]);
        }
    }

    // epilogue: BN/128 phases through fp32 smem staging [128][132]
    float* Cs = (float*)smem;
    constexpr int P = BN / 128;
    #pragma unroll
    for (int ph = 0; ph < P; ph++) {
        __syncthreads();
        if ((wn >> 7) == ph) {
            int cbase = wn & 127;
            #pragma unroll
            for (int i = 0; i < 4; i++)
                #pragma unroll
                for (int j = 0; j < CF::NJ; j++)
                    wmma::store_matrix_sync(Cs + (wm + i * 16) * G2_LDC + cbase + j * 16,
                                            acc[i][j], G2_LDC, wmma::mem_row_major);
        }
        __syncthreads();
        #pragma unroll
        for (int it = 0; it < 16; it++) {
            int idx = tid + 256 * it;
            int r = idx >> 5, c = (idx & 31) << 2;
            float4 v = *(float4*)(Cs + r * G2_LDC + c);
            if constexpr (sizeof(OutT) == 4) {
                *(float4*)((float*)C + (size_t)(bm + r) * N + bn + ph * 128 + c) = v;
            } else {
                half2 h0 = __floats2half2_rn(v.x, v.y);
                half2 h1 = __floats2half2_rn(v.z, v.w);
                *(uint2*)((half_t*)C + (size_t)(bm + r) * N + bn + ph * 128 + c) =
                    make_uint2(*(uint32_t*)&h0, *(uint32_t*)&h1);
            }
        }
    }
}

// =================== fused flash attention ================================
#define FL_RM   0
#define FL_QS   4096
#define FL_KS   (FL_QS + 18432)
#define FL_VS   (FL_KS + 18432)
#define FL_PS   (FL_VS + 18432)          // fp16 [128][136]
#define FL_OF   (FL_PS + 34816)          // fp32 [128][72]
#define FL_SF   (FL_OF + 36864)          // fp32 [128][132]
#define FL_M    (FL_SF + 67584)
#define FL_L    (FL_M + 512)
#define FL_CORR (FL_L + 512)
#define FL_SMEM (FL_CORR + 512)          // 200192

__global__ void __launch_bounds__(256, 1) flash_k(
    const half_t* __restrict__ qkv, const float* __restrict__ rmg,
    half_t* __restrict__ ctx)
{
    extern __shared__ __align__(128) char smem[];
    float*  rms = (float*)(smem + FL_RM);
    half_t* Qs  = (half_t*)(smem + FL_QS);
    half_t* Ks  = (half_t*)(smem + FL_KS);
    half_t* Vs  = (half_t*)(smem + FL_VS);
    half_t* Ps  = (half_t*)(smem + FL_PS);
    float*  Of  = (float*)(smem + FL_OF);
    float*  Sf  = (float*)(smem + FL_SF);
    float*  mS  = (float*)(smem + FL_M);
    float*  lS  = (float*)(smem + FL_L);
    float*  cS  = (float*)(smem + FL_CORR);

    const int tid = threadIdx.x, warp = tid >> 5;
    const int bz = blockIdx.y, b = bz >> 5, h = bz & 31;
    const int q0 = blockIdx.x * 128;

    for (int i = tid; i < 1023; i += 256) rms[i] = rmg[i];

    const half_t* qp = qkv + ((size_t)(b * 512 + q0)) * 6144 + h * 64;
    #pragma unroll
    for (int i = 0; i < 4; i++) {
        int idx = tid + 256 * i;
        int r = idx >> 3, c = (idx & 7) << 3;
        *(uint4*)(Qs + r * 72 + c) = *(const uint4*)(qp + (size_t)r * 6144 + c);
    }
    #pragma unroll
    for (int i = 0; i < 9; i++) {
        int idx = tid + 256 * i;
        *(float4*)(Of + idx * 4) = make_float4(0.f, 0.f, 0.f, 0.f);
    }
    if (tid < 128) { mS[tid] = -1e30f; lS[tid] = 0.0f; }
    __syncthreads();

    for (int kt = 0; kt < 4; kt++) {
        const int k0 = kt * 128;
        const half_t* kp = qkv + ((size_t)(b * 512 + k0)) * 6144 + 2048 + h * 64;
        const half_t* vp = qkv + ((size_t)(b * 512 + k0)) * 6144 + 4096 + h * 64;
        #pragma unroll
        for (int i = 0; i < 4; i++) {
            int idx = tid + 256 * i;
            int r = idx >> 3, c = (idx & 7) << 3;
            *(uint4*)(Ks + r * 72 + c) = *(const uint4*)(kp + (size_t)r * 6144 + c);
            *(uint4*)(Vs + r * 72 + c) = *(const uint4*)(vp + (size_t)r * 6144 + c);
        }
        __syncthreads();

        // ---- S = Q @ K^T ----
        {
            const int wm = (warp >> 2) * 64, wn = (warp & 3) * 32;
            wmma::fragment<wmma::accumulator, 16, 16, 16, float> sa[4][2];
            #pragma unroll
            for (int i = 0; i < 4; i++)
                #pragma unroll
                for (int j = 0; j < 2; j++)
                    wmma::fill_fragment(sa[i][j], 0.0f);
            #pragma unroll
            for (int ks = 0; ks < 4; ks++) {
                wmma::fragment<wmma::matrix_a, 16, 16, 16, half_t, wmma::row_major> af[4];
                wmma::fragment<wmma::matrix_b, 16, 16, 16, half_t, wmma::col_major> bf[2];
                #pragma unroll
                for (int i = 0; i < 4; i++)
                    wmma::load_matrix_sync(af[i], Qs + (wm + i * 16) * 72 + ks * 16, 72);
                #pragma unroll
                for (int j = 0; j < 2; j++)
                    wmma::load_matrix_sync(bf[j], Ks + (wn + j * 16) * 72 + ks * 16, 72);
                #pragma unroll
                for (int i = 0; i < 4; i++)
                    #pragma unroll
                    for (int j = 0; j < 2; j++)
                        wmma::mma_sync(sa[i][j], af[i], bf[j], sa[i][j]);
            }
            #pragma unroll
            for (int i = 0; i < 4; i++)
                #pragma unroll
                for (int j = 0; j < 2; j++)
                    wmma::store_matrix_sync(Sf + (wm + i * 16) * 132 + wn + j * 16,
                                            sa[i][j], 132, wmma::mem_row_major);
        }
        __syncthreads();

        // ---- online softmax ----
        {
            const int r = tid >> 1, hh = tid & 1, cb = hh * 64;
            float mx = -1e30f;
            #pragma unroll
            for (int c4 = 0; c4 < 16; c4++) {
                int col = cb + c4 * 4;
                float4 v = *(float4*)(Sf + r * 132 + col);
                int o = k0 + col - (q0 + r) + 511;
                v.x = v.x * 0.125f + rms[o];
                v.y = v.y * 0.125f + rms[o + 1];
                v.z = v.z * 0.125f + rms[o + 2];
                v.w = v.w * 0.125f + rms[o + 3];
                *(float4*)(Sf + r * 132 + col) = v;
                mx = fmaxf(mx, fmaxf(fmaxf(v.x, v.y), fmaxf(v.z, v.w)));
            }
            mx = fmaxf(mx, __shfl_xor_sync(0xffffffffu, mx, 1));
            float mo = mS[r];
            float mn = fmaxf(mo, mx);
            float co = __expf(mo - mn);
            float sum = 0.0f;
            #pragma unroll
            for (int c4 = 0; c4 < 16; c4++) {
                int col = cb + c4 * 4;
                float4 v = *(float4*)(Sf + r * 132 + col);
                float e0 = __expf(v.x - mn), e1 = __expf(v.y - mn);
                float e2 = __expf(v.z - mn), e3 = __expf(v.w - mn);
                sum += (e0 + e1) + (e2 + e3);
                half2 h0 = __floats2half2_rn(e0, e1);
                half2 h1 = __floats2half2_rn(e2, e3);
                *(uint2*)(Ps + r * 136 + col) =
                    make_uint2(*(uint32_t*)&h0, *(uint32_t*)&h1);
            }
            sum += __shfl_xor_sync(0xffffffffu, sum, 1);
            __syncwarp();
            if (hh == 0) {
                lS[r] = lS[r] * co + sum;
                mS[r] = mn;
                cS[r] = co;
            }
        }
        __syncthreads();

        // ---- PV ----
        {
            wmma::fragment<wmma::accumulator, 16, 16, 16, float> oa[4];
            #pragma unroll
            for (int j = 0; j < 4; j++) wmma::fill_fragment(oa[j], 0.0f);
            #pragma unroll
            for (int ks = 0; ks < 8; ks++) {
                wmma::fragment<wmma::matrix_a, 16, 16, 16, half_t, wmma::row_major> af;
                wmma::fragment<wmma::matrix_b, 16, 16, 16, half_t, wmma::row_major> bf[4];
                wmma::load_matrix_sync(af, Ps + (warp * 16) * 136 + ks * 16, 136);
                #pragma unroll
                for (int j = 0; j < 4; j++)
                    wmma::load_matrix_sync(bf[j], Vs + (ks * 16) * 72 + j * 16, 72);
                #pragma unroll
                for (int j = 0; j < 4; j++)
                    wmma::mma_sync(oa[j], af, bf[j], oa[j]);
            }
            float* St = Sf;
            #pragma unroll
            for (int j = 0; j < 4; j++)
                wmma::store_matrix_sync(St + (warp * 16) * 72 + j * 16,
                                        oa[j], 72, wmma::mem_row_major);
        }
        __syncthreads();

        // ---- O = O*corr + stage ----
        #pragma unroll
        for (int i = 0; i < 8; i++) {
            int idx = tid + 256 * i;
            int r = idx >> 4, c = (idx & 15) << 2;
            float cr = cS[r];
            float4 ov = *(float4*)(Of + r * 72 + c);
            float4 sv = *(float4*)(Sf + r * 72 + c);
            ov.x = ov.x * cr + sv.x;
            ov.y = ov.y * cr + sv.y;
            ov.z = ov.z * cr + sv.z;
            ov.w = ov.w * cr + sv.w;
            *(float4*)(Of + r * 72 + c) = ov;
        }
        __syncthreads();
    }

    half_t* cp = ctx + ((size_t)(b * 512 + q0)) * 2048 + h * 64;
    #pragma unroll
    for (int i = 0; i < 8; i++) {
        int idx = tid + 256 * i;
        int r = idx >> 4, c = (idx & 15) << 2;
        float li = 1.0f / lS[r];
        float4 ov = *(float4*)(Of + r * 72 + c);
        half2 h0 = __floats2half2_rn(ov.x * li, ov.y * li);
        half2 h1 = __floats2half2_rn(ov.z * li, ov.w * li);
        *(uint2*)(cp + (size_t)r * 2048 + c) =
            make_uint2(*(uint32_t*)&h0, *(uint32_t*)&h1);
    }
}

// ---------------- residual add + layernorm (row = 2048) ------------------
template <typename YT>
__global__ void __launch_bounds__(256) add_ln_k(
    const float* __restrict__ xr, const YT* __restrict__ yr,
    const float* __restrict__ g, const float* __restrict__ bt,
    float* __restrict__ out, half_t* __restrict__ hout)
{
    size_t row = blockIdx.x;
    const float4* xp = (const float4*)(xr + row * 2048);
    int t = threadIdx.x;
    float v[8];
    #pragma unroll
    for (int i = 0; i < 2; i++) {
        int c4 = t + 256 * i;
        float4 a = xp[c4];
        float yv[4];
        if constexpr (sizeof(YT) == 4) {
            float4 c = *(const float4*)((const float*)yr + row * 2048 + c4 * 4);
            yv[0] = c.x; yv[1] = c.y; yv[2] = c.z; yv[3] = c.w;
        } else {
            uint2 p = *(const uint2*)((const half_t*)yr + row * 2048 + c4 * 4);
            float2 f0 = __half22float2(*(half2*)&p.x);
            float2 f1 = __half22float2(*(half2*)&p.y);
            yv[0] = f0.x; yv[1] = f0.y; yv[2] = f1.x; yv[3] = f1.y;
        }
        v[4 * i + 0] = a.x + yv[0]; v[4 * i + 1] = a.y + yv[1];
        v[4 * i + 2] = a.z + yv[2]; v[4 * i + 3] = a.w + yv[3];
    }
    float s = 0.0f;
    #pragma unroll
    for (int i = 0; i < 8; i++) s += v[i];
    float mu = bred(s, 0) * (1.0f / 2048.0f);
    float qs = 0.0f;
    #pragma unroll
    for (int i = 0; i < 8; i++) { float d = v[i] - mu; qs += d * d; }
    float rstd = rsqrtf(bred(qs, 0) * (1.0f / 2048.0f) + 1e-6f);
    float4* op = (float4*)(out + row * 2048);
    #pragma unroll
    for (int i = 0; i < 2; i++) {
        int c4 = t + 256 * i;
        float4 gv = ((const float4*)g)[c4];
        float4 bv = ((const float4*)bt)[c4];
        float4 o;
        o.x = (v[4 * i + 0] - mu) * rstd * gv.x + bv.x;
        o.y = (v[4 * i + 1] - mu) * rstd * gv.y + bv.y;
        o.z = (v[4 * i + 2] - mu) * rstd * gv.z + bv.z;
        o.w = (v[4 * i + 3] - mu) * rstd * gv.w + bv.w;
        op[c4] = o;
        if (hout) {
            half2 h0 = __floats2half2_rn(o.x, o.y);
            half2 h1 = __floats2half2_rn(o.z, o.w);
            *(uint2*)(hout + row * 2048 + c4 * 4) =
                make_uint2(*(uint32_t*)&h0, *(uint32_t*)&h1);
        }
    }
}

// ---------------- silu(gate)*up (fp16 in) -> fp16 act ---------------------
__global__ void __launch_bounds__(256) silu_mul_h(
    const half_t* __restrict__ gate, const half_t* __restrict__ up,
    half_t* __restrict__ act)
{
    size_t i = (size_t)blockIdx.x * 256 + threadIdx.x;
    uint4 gp = ((const uint4*)gate)[i];
    uint4 upk = ((const uint4*)up)[i];
    const half2* g2 = (const half2*)&gp;
    const half2* u2 = (const half2*)&upk;
    uint4 r;
    half2* r2 = (half2*)&r;
    #pragma unroll
    for (int j = 0; j < 4; j++) {
        float2 gf = __half22float2(g2[j]);
        float2 uf = __half22float2(u2[j]);
        float a = gf.x / (1.0f + __expf(-gf.x)) * uf.x;
        float b = gf.y / (1.0f + __expf(-gf.y)) * uf.y;
        r2[j] = __floats2half2_rn(a, b);
    }
    ((uint4*)act)[i] = r;
}

// ---------------- mega conversion: ALL fp32->fp16 + rel rowmean -----------
__device__ __forceinline__ void conv16(const float* in, half_t* out) {
    float4 a0 = *(const float4*)(in + 0);
    float4 a1 = *(const float4*)(in + 4);
    float4 a2 = *(const float4*)(in + 8);
    float4 a3 = *(const float4*)(in + 12);
    half2 h0 = __floats2half2_rn(a0.x, a0.y), h1 = __floats2half2_rn(a0.z, a0.w);
    half2 h2 = __floats2half2_rn(a1.x, a1.y), h3 = __floats2half2_rn(a1.z, a1.w);
    half2 h4 = __floats2half2_rn(a2.x, a2.y), h5 = __floats2half2_rn(a2.z, a2.w);
    half2 h6 = __floats2half2_rn(a3.x, a3.y), h7 = __floats2half2_rn(a3.z, a3.w);
    *(uint4*)(out + 0) = make_uint4(*(uint32_t*)&h0, *(uint32_t*)&h1,
                                    *(uint32_t*)&h2, *(uint32_t*)&h3);
    *(uint4*)(out + 8) = make_uint4(*(uint32_t*)&h4, *(uint32_t*)&h5,
                                    *(uint32_t*)&h6, *(uint32_t*)&h7);
}

__global__ void __launch_bounds__(256) conv_all(
    const float* __restrict__ x,  half_t* __restrict__ xo,
    const float* __restrict__ wq, const float* __restrict__ wk,
    const float* __restrict__ wv, half_t* __restrict__ wqkv,
    const float* __restrict__ wo, half_t* __restrict__ woo,
    const float* __restrict__ gw, half_t* __restrict__ gwo,
    const float* __restrict__ uw, half_t* __restrict__ uwo,
    const float* __restrict__ dw, half_t* __restrict__ dwo,
    const float* __restrict__ rel, float* __restrict__ rm)
{
    int blk = blockIdx.x;
    const int t = threadIdx.x;

    if (blk >= 18432) {
        int r = (blk - 18432) * 256 + t;
        if (r < 1023) {
            float s = 0.0f;
            #pragma unroll
            for (int d = 0; d < 64; d += 4) {
                float4 vv = *(const float4*)(rel + (size_t)r * 64 + d);
                s += (vv.x + vv.y) + (vv.z + vv.w);
            }
            rm[r] = s * (1.0f / 64.0f);
        }
        return;
    }

    if (blk < 2048) {
        size_t i = ((size_t)blk * 256 + t) * 16;
        conv16(x + i, xo + i);
        return;
    }
    if (blk < 5120) {
        int sec = (blk - 2048) >> 10;
        const float* in = sec == 0 ? wq : (sec == 1 ? wk : wv);
        size_t i = ((size_t)((blk - 2048) & 1023) * 256 + t) * 16;
        int r = (int)(i >> 11), c = (int)(i & 2047);
        conv16(in + i, wqkv + (size_t)r * 6144 + sec * 2048 + c);
        return;
    }
    if (blk < 6144) {
        size_t i = ((size_t)(blk - 5120) * 256 + t) * 16;
        conv16(wo + i, woo + i);
        return;
    }
    if (blk < 10240) {
        size_t i = ((size_t)(blk - 6144) * 256 + t) * 16;
        conv16(gw + i, gwo + i);
        return;
    }
    if (blk < 14336) {
        size_t i = ((size_t)(blk - 10240) * 256 + t) * 16;
        conv16(uw + i, uwo + i);
        return;
    }
    size_t i = ((size_t)(blk - 14336) * 256 + t) * 16;
    conv16(dw + i, dwo + i);
}

// =================== host side ============================================
extern "C" void kernel_launch(void* const* d_in, const int* in_sizes, int n_in,
                              void* d_out, int out_size)
{
    (void)in_sizes; (void)n_in; (void)out_size;
    const float* x    = (const float*)d_in[0];
    const float* wq   = (const float*)d_in[1];
    const float* wk   = (const float*)d_in[2];
    const float* wv   = (const float*)d_in[3];
    const float* wo   = (const float*)d_in[4];
    const float* rel  = (const float*)d_in[5];
    const float* ln1g = (const float*)d_in[6];
    const float* ln1b = (const float*)d_in[7];
    const float* gw   = (const float*)d_in[8];
    const float* uw   = (const float*)d_in[9];
    const float* dw   = (const float*)d_in[10];
    const float* ln2g = (const float*)d_in[11];
    const float* ln2b = (const float*)d_in[12];
    float* out = (float*)d_out;

    float *tmp, *up, *h1, *rm;
    half_t *xh, *qkvh, *ctxh, *h1h, *acth;
    half_t *wqkvh, *woh, *gwh, *uwh, *dwh;
    cudaGetSymbolAddress((void**)&tmp,   g_tmp);
    cudaGetSymbolAddress((void**)&up,    g_up);
    cudaGetSymbolAddress((void**)&h1,    g_h1);
    cudaGetSymbolAddress((void**)&rm,    g_rm);
    cudaGetSymbolAddress((void**)&xh,    g_xh);
    cudaGetSymbolAddress((void**)&qkvh,  g_qkvh);
    cudaGetSymbolAddress((void**)&ctxh,  g_ctxh);
    cudaGetSymbolAddress((void**)&h1h,   g_h1h);
    cudaGetSymbolAddress((void**)&acth,  g_acth);
    cudaGetSymbolAddress((void**)&wqkvh, g_wqkvh);
    cudaGetSymbolAddress((void**)&woh,   g_woh);
    cudaGetSymbolAddress((void**)&gwh,   g_gwh);
    cudaGetSymbolAddress((void**)&uwh,   g_uwh);
    cudaGetSymbolAddress((void**)&dwh,   g_dwh);

    half_t* gate_h = (half_t*)tmp;
    half_t* up_h   = (half_t*)up;
    half_t* attn_h = acth;
    float*  ffn_f  = (float*)up;

    cudaFuncSetAttribute((const void*)gemm2<256, half_t>,
        cudaFuncAttributeMaxDynamicSharedMemorySize, G2C<256>::SMEM);
    cudaFuncSetAttribute((const void*)gemm2<128, half_t>,
        cudaFuncAttributeMaxDynamicSharedMemorySize, G2C<128>::SMEM);
    cudaFuncSetAttribute((const void*)gemm2<128, float>,
        cudaFuncAttributeMaxDynamicSharedMemorySize, G2C<128>::SMEM);
    cudaFuncSetAttribute((const void*)flash_k,
        cudaFuncAttributeMaxDynamicSharedMemorySize, FL_SMEM);

    // #1: all conversions + rowmean in one launch
    conv_all<<<18436, 256>>>(x, xh, wq, wk, wv, wqkvh, wo, woh,
                             gw, gwh, uw, uwh, dw, dwh, rel, rm);

    // #2: fused QKV projection (profiled launch)
    gemm2<256, half_t><<<dim3(24, 32), 256, G2C<256>::SMEM>>>(
        xh, wqkvh, qkvh, 4096, 6144, 2048);

    // #3: fused flash attention
    flash_k<<<dim3(4, 256), 256, FL_SMEM>>>(qkvh, rm, ctxh);

    // #4-5: output projection (128-wide tiles, 512 CTAs) + residual + LN1
    gemm2<128, half_t><<<dim3(16, 32), 256, G2C<128>::SMEM>>>(
        ctxh, woh, attn_h, 4096, 2048, 2048);
    add_ln_k<half_t><<<4096, 256>>>(x, attn_h, ln1g, ln1b, h1, h1h);

    // #6-9: FFN (SwiGLU)
    gemm2<256, half_t><<<dim3(32, 32), 256, G2C<256>::SMEM>>>(
        h1h, gwh, gate_h, 4096, 8192, 2048);
    gemm2<256, half_t><<<dim3(32, 32), 256, G2C<256>::SMEM>>>(
        h1h, uwh, up_h, 4096, 8192, 2048);
    silu_mul_h<<<16384, 256>>>(gate_h, up_h, acth);
    gemm2<128, float><<<dim3(16, 32), 256, G2C<128>::SMEM>>>(
        acth, dwh, ffn_f, 4096, 2048, 8192);

    // #10: residual + LN2 -> output
    add_ln_k<float><<<4096, 256>>>(h1, ffn_f, ln2g, ln2b, out, nullptr);
}